// round 1
// baseline (speedup 1.0000x reference)
#include <cuda_runtime.h>
#include <math.h>

#define BATCH 32768
#define S 3
#define L 5
#define D1 32
#define D2 64
#define OUT 541
#define KDIM 320      // D2*L
#define NPAD 576      // padded N for GEMM tiles (9 x 64)
#define EPSBN 1e-5f

// ---- device scratch (static: no allocations allowed) ----
__device__ float g_h2[(size_t)S * KDIM * BATCH];   // [s][j][b], j = d2*L + l
__device__ float g_sum1[S * KDIM];
__device__ float g_sum2[S * KDIM];
__device__ float g_scale[S * D2];
__device__ float g_shift[S * D2];
__device__ float g_wlT[(size_t)S * KDIM * NPAD];   // [s][j][o], BN scale folded in
__device__ float g_bias[S * OUT];                  // BN shift folded in

__device__ __forceinline__ float gelu_exact(float v) {
    return 0.5f * v * (1.0f + erff(v * 0.70710678118654752f));
}

// ============================================================================
// K1: per (b,s) conv1 -> gelu -> conv2 -> gelu, write h2 to scratch [s][j][b]
// ============================================================================
__global__ __launch_bounds__(128, 1) void k1_conv(
    const float* __restrict__ x,  const float* __restrict__ w1,
    const float* __restrict__ b1, const float* __restrict__ w2,
    const float* __restrict__ b2)
{
    __shared__ __align__(16) float w1s[D1 * 3];
    __shared__ float b1s[D1];
    __shared__ __align__(16) float w2s[3 * D2 * D1];  // [k][d2][d1] for vector LDS
    __shared__ float b2s[D2];

    const int s = blockIdx.y;
    const int tid = threadIdx.x;

    for (int i = tid; i < D1 * 3; i += 128) w1s[i] = w1[s * D1 * 3 + i];
    for (int i = tid; i < D1; i += 128)     b1s[i] = b1[s * D1 + i];
    for (int i = tid; i < D2; i += 128)     b2s[i] = b2[s * D2 + i];
    for (int i = tid; i < 3 * D2 * D1; i += 128) {
        int d2 = i / (D1 * 3);
        int r  = i % (D1 * 3);
        int d1 = r / 3;
        int k  = r % 3;
        w2s[(k * D2 + d2) * D1 + d1] = w2[s * D2 * D1 * 3 + i];
    }
    __syncthreads();

    const int b = blockIdx.x * 128 + tid;   // BATCH divisible by 128

    // padded input window
    float xp[L + 2];
    xp[0] = 0.0f; xp[L + 1] = 0.0f;
    #pragma unroll
    for (int l = 0; l < L; ++l) xp[l + 1] = x[(b * S + s) * L + l];

    // conv1 + gelu: h1[l][d1], fully register-resident (static indices only)
    float h1[L][D1];
    #pragma unroll
    for (int l = 0; l < L; ++l) {
        #pragma unroll
        for (int d1 = 0; d1 < D1; ++d1) {
            float v = b1s[d1]
                    + w1s[d1 * 3 + 0] * xp[l]
                    + w1s[d1 * 3 + 1] * xp[l + 1]
                    + w1s[d1 * 3 + 2] * xp[l + 2];
            h1[l][d1] = gelu_exact(v);
        }
    }

    // conv2 + gelu, streaming over d2; 5 independent accumulators for ILP
    float* outp = &g_h2[(size_t)s * KDIM * BATCH + b];
    for (int d2 = 0; d2 < D2; ++d2) {
        float acc[L];
        #pragma unroll
        for (int l = 0; l < L; ++l) acc[l] = b2s[d2];
        #pragma unroll
        for (int k = 0; k < 3; ++k) {
            const float4* wp = (const float4*)&w2s[(k * D2 + d2) * D1];
            #pragma unroll
            for (int q = 0; q < D1 / 4; ++q) {
                float4 w = wp[q];
                #pragma unroll
                for (int l = 0; l < L; ++l) {
                    int c = l + k - 1;
                    if (c >= 0 && c < L) {
                        acc[l] += w.x * h1[c][q * 4 + 0] + w.y * h1[c][q * 4 + 1]
                                + w.z * h1[c][q * 4 + 2] + w.w * h1[c][q * 4 + 3];
                    }
                }
            }
        }
        #pragma unroll
        for (int l = 0; l < L; ++l) {
            outp[(size_t)(d2 * L + l) * BATCH] = gelu_exact(acc[l]);  // coalesced in b
        }
    }
}

// ============================================================================
// K2: per (s,j) column sum / sumsq over b (deterministic tree reduce, no atomics)
// ============================================================================
__global__ void k2_stats()
{
    const int j = blockIdx.x, s = blockIdx.y, tid = threadIdx.x;
    const float* p = &g_h2[(size_t)(s * KDIM + j) * BATCH];
    float s1 = 0.0f, s2 = 0.0f;
    for (int i = tid; i < BATCH; i += 256) {
        float v = p[i];
        s1 += v;
        s2 += v * v;
    }
    __shared__ float r1[256], r2[256];
    r1[tid] = s1; r2[tid] = s2;
    __syncthreads();
    for (int off = 128; off > 0; off >>= 1) {
        if (tid < off) { r1[tid] += r1[tid + off]; r2[tid] += r2[tid + off]; }
        __syncthreads();
    }
    if (tid == 0) {
        g_sum1[s * KDIM + j] = r1[0];
        g_sum2[s * KDIM + j] = r2[0];
    }
}

// ============================================================================
// K3a: finalize BN per (s,d2): scale = gamma*inv_std, shift = beta - mean*scale
// ============================================================================
__global__ void k3_finalize(const float* __restrict__ gamma, const float* __restrict__ beta)
{
    int t = threadIdx.x;
    if (t >= S * D2) return;
    int s = t / D2, d2 = t % D2;
    float S1 = 0.0f, S2 = 0.0f;
    #pragma unroll
    for (int l = 0; l < L; ++l) {
        S1 += g_sum1[s * KDIM + d2 * L + l];
        S2 += g_sum2[s * KDIM + d2 * L + l];
    }
    const float invn = 1.0f / (float)(BATCH * L);
    float mean = S1 * invn;
    float var  = S2 * invn - mean * mean;
    float inv  = rsqrtf(var + EPSBN);
    float sc   = gamma[t] * inv;
    g_scale[t] = sc;
    g_shift[t] = beta[t] - mean * sc;
}

// ============================================================================
// K3b: build transposed, scale-folded weights wlT[s][j][o] (o padded to 576)
// ============================================================================
__global__ void k3_wT(const float* __restrict__ wl)
{
    int j = blockIdx.x, s = blockIdx.y, o = threadIdx.x;  // 576 threads
    float sc = g_scale[s * D2 + j / L];
    float v = (o < OUT) ? wl[((size_t)s * OUT + o) * KDIM + j] * sc : 0.0f;
    g_wlT[(size_t)(s * KDIM + j) * NPAD + o] = v;
}

// ============================================================================
// K3c: effective bias b'[s][o] = bl + sum_j wl[o][j] * shift[j/5]
// ============================================================================
__global__ void k3_bias(const float* __restrict__ wl, const float* __restrict__ bl)
{
    int o = blockIdx.x, s = blockIdx.y, j = threadIdx.x;  // 320 threads
    float v = wl[((size_t)s * OUT + o) * KDIM + j] * g_shift[s * D2 + j / L];
    __shared__ float red[KDIM];
    red[j] = v;
    __syncthreads();
    if (j < 64)  red[j] += red[j + 256];
    __syncthreads();
    if (j < 128) red[j] += red[j + 128];
    __syncthreads();
    if (j < 64)  red[j] += red[j + 64];
    __syncthreads();
    if (j < 32) {
        float xv = red[j] + red[j + 32];
        #pragma unroll
        for (int off = 16; off > 0; off >>= 1)
            xv += __shfl_down_sync(0xffffffffu, xv, off);
        if (j == 0) g_bias[s * OUT + o] = bl[s * OUT + o] + xv;
    }
}

// ============================================================================
// K4: GEMM  out[b][s][o] = sum_j h2[s][j][b] * wlT[s][j][o] + bias[s][o]
//     64x64 block tile, 16 K-tile, 256 threads, 4x4 microtile
// ============================================================================
__global__ __launch_bounds__(256) void k4_gemm(float* __restrict__ out)
{
    __shared__ __align__(16) float As[16][68];
    __shared__ __align__(16) float Bs[16][68];

    const int s  = blockIdx.z;
    const int bt = blockIdx.x * 64;   // M tile (batch), 32768/64 = 512 tiles
    const int nt = blockIdx.y * 64;   // N tile (out),   576/64   = 9 tiles
    const int tid = threadIdx.x;
    const int tx = tid & 15, ty = tid >> 4;
    const int lr = tid >> 4;          // load row (k within tile)
    const int lc = (tid & 15) * 4;    // load col (float4)

    const float* Ab = &g_h2 [(size_t)s * KDIM * BATCH + bt];
    const float* Bb = &g_wlT[(size_t)s * KDIM * NPAD  + nt];

    float acc[4][4] = {};

    for (int kt = 0; kt < KDIM; kt += 16) {
        *(float4*)&As[lr][lc] = *(const float4*)&Ab[(size_t)(kt + lr) * BATCH + lc];
        *(float4*)&Bs[lr][lc] = *(const float4*)&Bb[(size_t)(kt + lr) * NPAD  + lc];
        __syncthreads();
        #pragma unroll
        for (int kk = 0; kk < 16; ++kk) {
            float4 a  = *(const float4*)&As[kk][ty * 4];
            float4 bv = *(const float4*)&Bs[kk][tx * 4];
            float av[4] = {a.x, a.y, a.z, a.w};
            float bw[4] = {bv.x, bv.y, bv.z, bv.w};
            #pragma unroll
            for (int i = 0; i < 4; ++i)
                #pragma unroll
                for (int jj = 0; jj < 4; ++jj)
                    acc[i][jj] += av[i] * bw[jj];
        }
        __syncthreads();
    }

    #pragma unroll
    for (int i = 0; i < 4; ++i) {
        int b = bt + ty * 4 + i;
        float* orow = &out[((size_t)b * S + s) * OUT];
        #pragma unroll
        for (int jj = 0; jj < 4; ++jj) {
            int o = nt + tx * 4 + jj;
            if (o < OUT) orow[o] = acc[i][jj] + g_bias[s * OUT + o];
        }
    }
}

// ============================================================================
extern "C" void kernel_launch(void* const* d_in, const int* in_sizes, int n_in,
                              void* d_out, int out_size)
{
    const float* x     = (const float*)d_in[0];
    const float* w1    = (const float*)d_in[1];
    const float* b1    = (const float*)d_in[2];
    const float* w2    = (const float*)d_in[3];
    const float* b2    = (const float*)d_in[4];
    const float* gamma = (const float*)d_in[5];
    const float* beta  = (const float*)d_in[6];
    const float* wl    = (const float*)d_in[7];
    const float* bl    = (const float*)d_in[8];
    float* out = (float*)d_out;

    k1_conv    <<<dim3(BATCH / 128, S), 128>>>(x, w1, b1, w2, b2);
    k2_stats   <<<dim3(KDIM, S), 256>>>();
    k3_finalize<<<1, 192>>>(gamma, beta);
    k3_wT      <<<dim3(KDIM, S), NPAD>>>(wl);
    k3_bias    <<<dim3(OUT, S), KDIM>>>(wl, bl);
    k4_gemm    <<<dim3(BATCH / 64, NPAD / 64, S), 256>>>(out);
}

// round 5
// speedup vs baseline: 1.7100x; 1.7100x over previous
#include <cuda_runtime.h>
#include <cuda_bf16.h>
#include <math.h>
#include <stdint.h>

#define BATCH 32768
#define S 3
#define L 5
#define D1 32
#define D2 64
#define OUT 541
#define KDIM 320      // D2*L
#define NPAD 576      // padded N (3 x 192)
#define EPSBN 1e-5f

// GEMM tiling
#define BM 128
#define BN 192
#define BK 32
#define NCHUNK (KDIM / BK)      // 10
#define A_BYTES (BM * 64)       // 8192
#define B_BYTES (BN * 64)       // 12288
#define STAGE_BYTES (2 * A_BYTES + 2 * B_BYTES)  // 40960
#define DSMEM (2 * STAGE_BYTES) // 81920

// ---- device scratch (static: no allocations allowed) ----
__device__ __align__(16) float g_h2[(size_t)S * KDIM * BATCH];            // [s][j][b]
__device__ __align__(16) __nv_bfloat16 g_ahi[(size_t)S * BATCH * KDIM];   // [s][b][j]
__device__ __align__(16) __nv_bfloat16 g_alo[(size_t)S * BATCH * KDIM];
__device__ __align__(16) __nv_bfloat16 g_bhi[(size_t)S * NPAD * KDIM];    // [s][o][j]
__device__ __align__(16) __nv_bfloat16 g_blo[(size_t)S * NPAD * KDIM];
__device__ float g_sum1[S * KDIM];
__device__ float g_sum2[S * KDIM];
__device__ float g_scale[S * D2];
__device__ float g_shift[S * D2];
__device__ float g_bias[S * OUT];

__device__ __forceinline__ float gelu_exact(float v) {
    return 0.5f * v * (1.0f + erff(v * 0.70710678118654752f));
}

// ---------------- portable PTX helpers (sm_80-era instructions only) --------
__device__ __forceinline__ uint32_t smem_u32(const void* p) {
    uint32_t a;
    asm("{ .reg .u64 t; cvta.to.shared.u64 t, %1; cvt.u32.u64 %0, t; }" : "=r"(a) : "l"(p));
    return a;
}
__device__ __forceinline__ void cp16(uint32_t dst, const void* src) {
    asm volatile("cp.async.cg.shared.global [%0], [%1], 16;" :: "r"(dst), "l"(src));
}
__device__ __forceinline__ void cp_commit() {
    asm volatile("cp.async.commit_group;" ::: "memory");
}
template<int N> __device__ __forceinline__ void cp_wait() {
    asm volatile("cp.async.wait_group %0;" :: "n"(N) : "memory");
}
__device__ __forceinline__ void ldm_x4(uint32_t& r0, uint32_t& r1, uint32_t& r2, uint32_t& r3,
                                       uint32_t addr) {
    asm volatile("ldmatrix.sync.aligned.m8n8.x4.shared.b16 {%0,%1,%2,%3}, [%4];"
                 : "=r"(r0), "=r"(r1), "=r"(r2), "=r"(r3) : "r"(addr));
}
__device__ __forceinline__ void mma16816(float* c, const uint32_t* a, const uint32_t* b) {
    asm volatile(
        "mma.sync.aligned.m16n8k16.row.col.f32.bf16.bf16.f32 "
        "{%0,%1,%2,%3}, {%4,%5,%6,%7}, {%8,%9}, {%0,%1,%2,%3};"
        : "+f"(c[0]), "+f"(c[1]), "+f"(c[2]), "+f"(c[3])
        : "r"(a[0]), "r"(a[1]), "r"(a[2]), "r"(a[3]), "r"(b[0]), "r"(b[1]));
}
// swizzled smem offset: 64B rows, 16B granules
__device__ __forceinline__ uint32_t swz_off(int row, int g) {
    return (uint32_t)(row * 64 + ((g ^ ((row >> 1) & 3)) << 4));
}

// ============================================================================
// K1: per (b,s) conv1 -> gelu -> conv2 -> gelu, write h2 [s][j][b]
// ============================================================================
__global__ __launch_bounds__(128, 1) void k1_conv(
    const float* __restrict__ x,  const float* __restrict__ w1,
    const float* __restrict__ b1, const float* __restrict__ w2,
    const float* __restrict__ b2)
{
    __shared__ __align__(16) float w1s[D1 * 3];
    __shared__ float b1s[D1];
    __shared__ __align__(16) float w2s[3 * D2 * D1];
    __shared__ float b2s[D2];

    const int s = blockIdx.y;
    const int tid = threadIdx.x;

    for (int i = tid; i < D1 * 3; i += 128) w1s[i] = w1[s * D1 * 3 + i];
    for (int i = tid; i < D1; i += 128)     b1s[i] = b1[s * D1 + i];
    for (int i = tid; i < D2; i += 128)     b2s[i] = b2[s * D2 + i];
    for (int i = tid; i < 3 * D2 * D1; i += 128) {
        int d2 = i / (D1 * 3);
        int r  = i % (D1 * 3);
        int d1 = r / 3;
        int k  = r % 3;
        w2s[(k * D2 + d2) * D1 + d1] = w2[s * D2 * D1 * 3 + i];
    }
    __syncthreads();

    const int b = blockIdx.x * 128 + tid;

    float xp[L + 2];
    xp[0] = 0.0f; xp[L + 1] = 0.0f;
    #pragma unroll
    for (int l = 0; l < L; ++l) xp[l + 1] = x[(b * S + s) * L + l];

    float h1[L][D1];
    #pragma unroll
    for (int l = 0; l < L; ++l) {
        #pragma unroll
        for (int d1 = 0; d1 < D1; ++d1) {
            float v = b1s[d1]
                    + w1s[d1 * 3 + 0] * xp[l]
                    + w1s[d1 * 3 + 1] * xp[l + 1]
                    + w1s[d1 * 3 + 2] * xp[l + 2];
            h1[l][d1] = gelu_exact(v);
        }
    }

    float* outp = &g_h2[(size_t)s * KDIM * BATCH + b];
    for (int d2 = 0; d2 < D2; ++d2) {
        float acc[L];
        #pragma unroll
        for (int l = 0; l < L; ++l) acc[l] = b2s[d2];
        #pragma unroll
        for (int k = 0; k < 3; ++k) {
            const float4* wp = (const float4*)&w2s[(k * D2 + d2) * D1];
            #pragma unroll
            for (int q = 0; q < D1 / 4; ++q) {
                float4 w = wp[q];
                #pragma unroll
                for (int l = 0; l < L; ++l) {
                    int c = l + k - 1;
                    if (c >= 0 && c < L) {
                        acc[l] += w.x * h1[c][q * 4 + 0] + w.y * h1[c][q * 4 + 1]
                                + w.z * h1[c][q * 4 + 2] + w.w * h1[c][q * 4 + 3];
                    }
                }
            }
        }
        #pragma unroll
        for (int l = 0; l < L; ++l) {
            outp[(size_t)(d2 * L + l) * BATCH] = gelu_exact(acc[l]);
        }
    }
}

// ============================================================================
// K2: per (s,j) sum / sumsq over b
// ============================================================================
__global__ void k2_stats()
{
    const int j = blockIdx.x, s = blockIdx.y, tid = threadIdx.x;
    const float* p = &g_h2[(size_t)(s * KDIM + j) * BATCH];
    float s1 = 0.0f, s2 = 0.0f;
    for (int i = tid; i < BATCH; i += 256) {
        float v = p[i];
        s1 += v;
        s2 += v * v;
    }
    __shared__ float r1[256], r2[256];
    r1[tid] = s1; r2[tid] = s2;
    __syncthreads();
    for (int off = 128; off > 0; off >>= 1) {
        if (tid < off) { r1[tid] += r1[tid + off]; r2[tid] += r2[tid + off]; }
        __syncthreads();
    }
    if (tid == 0) {
        g_sum1[s * KDIM + j] = r1[0];
        g_sum2[s * KDIM + j] = r2[0];
    }
}

// ============================================================================
// K3a: BN finalize
// ============================================================================
__global__ void k3_finalize(const float* __restrict__ gamma, const float* __restrict__ beta)
{
    int t = threadIdx.x;
    if (t >= S * D2) return;
    int s = t / D2, d2 = t % D2;
    float S1 = 0.0f, S2 = 0.0f;
    #pragma unroll
    for (int l = 0; l < L; ++l) {
        S1 += g_sum1[s * KDIM + d2 * L + l];
        S2 += g_sum2[s * KDIM + d2 * L + l];
    }
    const float invn = 1.0f / (float)(BATCH * L);
    float mean = S1 * invn;
    float var  = S2 * invn - mean * mean;
    float inv  = rsqrtf(var + EPSBN);
    float sc   = gamma[t] * inv;
    g_scale[t] = sc;
    g_shift[t] = beta[t] - mean * sc;
}

// ============================================================================
// K_split: transpose g_h2 [s][j][b] -> bf16 hi/lo [s][b][j]
// ============================================================================
__global__ __launch_bounds__(256) void k_split()
{
    __shared__ float tsm[64][33];
    const int s  = blockIdx.z;
    const int j0 = blockIdx.x * 64;
    const int b0 = blockIdx.y * 32;
    const int tx = threadIdx.x & 31, ty = threadIdx.x >> 5;

    #pragma unroll
    for (int r = 0; r < 8; ++r) {
        int j = ty + 8 * r;
        tsm[j][tx] = g_h2[(size_t)(s * KDIM + j0 + j) * BATCH + b0 + tx];
    }
    __syncthreads();

    #pragma unroll
    for (int r = 0; r < 4; ++r) {
        int brow = ty + 8 * r;
        float v0 = tsm[2 * tx + 0][brow];
        float v1 = tsm[2 * tx + 1][brow];
        __nv_bfloat16 h0 = __float2bfloat16(v0);
        __nv_bfloat16 h1v = __float2bfloat16(v1);
        __nv_bfloat16 l0 = __float2bfloat16(v0 - __bfloat162float(h0));
        __nv_bfloat16 l1 = __float2bfloat16(v1 - __bfloat162float(h1v));
        size_t base = ((size_t)(s * BATCH + b0 + brow)) * KDIM + j0 + 2 * tx;
        __nv_bfloat162 ph; ph.x = h0; ph.y = h1v;
        __nv_bfloat162 pl; pl.x = l0; pl.y = l1;
        *(__nv_bfloat162*)&g_ahi[base] = ph;
        *(__nv_bfloat162*)&g_alo[base] = pl;
    }
}

// ============================================================================
// K3b: scale-folded, transposed, split weights -> bf16 hi/lo [s][o][j]
// ============================================================================
__global__ void k3_bsplit(const float* __restrict__ wl)
{
    int o = blockIdx.x, s = blockIdx.y, j = threadIdx.x;  // 320 threads
    float v = 0.0f;
    if (o < OUT) v = wl[((size_t)s * OUT + o) * KDIM + j] * g_scale[s * D2 + j / L];
    __nv_bfloat16 hi = __float2bfloat16(v);
    __nv_bfloat16 lo = __float2bfloat16(v - __bfloat162float(hi));
    size_t base = ((size_t)(s * NPAD + o)) * KDIM + j;
    g_bhi[base] = hi;
    g_blo[base] = lo;
}

// ============================================================================
// K3c: effective bias
// ============================================================================
__global__ void k3_bias(const float* __restrict__ wl, const float* __restrict__ bl)
{
    int o = blockIdx.x, s = blockIdx.y, j = threadIdx.x;  // 320 threads
    float v = wl[((size_t)s * OUT + o) * KDIM + j] * g_shift[s * D2 + j / L];
    __shared__ float red[KDIM];
    red[j] = v;
    __syncthreads();
    if (j < 64)  red[j] += red[j + 256];
    __syncthreads();
    if (j < 128) red[j] += red[j + 128];
    __syncthreads();
    if (j < 64)  red[j] += red[j + 64];
    __syncthreads();
    if (j < 32) {
        float xv = red[j] + red[j + 32];
        #pragma unroll
        for (int off = 16; off > 0; off >>= 1)
            xv += __shfl_down_sync(0xffffffffu, xv, off);
        if (j == 0) g_bias[s * OUT + o] = bl[s * OUT + o] + xv;
    }
}

// ============================================================================
// K6: HMMA split-GEMM.  out = Ahi*Bhi + Ahi*Blo + Alo*Bhi (+bias)
//   CTA 128x192, BK=32, double-buffered cp.async, mma.sync m16n8k16 bf16
// ============================================================================
__global__ __launch_bounds__(256, 1) void k6_gemm(float* __restrict__ out)
{
    extern __shared__ __align__(16) char dyn[];
    const uint32_t sbase = smem_u32(dyn);

    const int tid  = threadIdx.x;
    const int wid  = tid >> 5;
    const int lane = tid & 31;
    const int nt = blockIdx.x * BN;   // 0,192,384 (fastest -> A L2 reuse)
    const int bt = blockIdx.y * BM;
    const int s  = blockIdx.z;

    const int wm = (wid & 3) * 32;    // warp m offset
    const int wn = (wid >> 2) * 96;   // warp n offset

    const __nv_bfloat16* Ah = g_ahi + ((size_t)(s * BATCH + bt)) * KDIM;
    const __nv_bfloat16* Al = g_alo + ((size_t)(s * BATCH + bt)) * KDIM;
    const __nv_bfloat16* Bh = g_bhi + ((size_t)(s * NPAD + nt)) * KDIM;
    const __nv_bfloat16* Bl = g_blo + ((size_t)(s * NPAD + nt)) * KDIM;

    float c[2][12][4];
    #pragma unroll
    for (int i = 0; i < 2; ++i)
        #pragma unroll
        for (int j = 0; j < 12; ++j)
            #pragma unroll
            for (int k = 0; k < 4; ++k) c[i][j][k] = 0.0f;

    auto load_stage = [&](int chunk) {
        const uint32_t st = sbase + (uint32_t)(chunk & 1) * STAGE_BYTES;
        const int coff = chunk * BK;
        #pragma unroll
        for (int u = tid; u < BM * 4; u += 256) {
            int row = u >> 2, g = u & 3;
            uint32_t so = swz_off(row, g);
            cp16(st + so,          (const char*)(Ah + (size_t)row * KDIM + coff) + g * 16);
            cp16(st + A_BYTES + so,(const char*)(Al + (size_t)row * KDIM + coff) + g * 16);
        }
        #pragma unroll
        for (int u = tid; u < BN * 4; u += 256) {
            int row = u >> 2, g = u & 3;
            uint32_t so = swz_off(row, g);
            cp16(st + 2 * A_BYTES + so,
                 (const char*)(Bh + (size_t)row * KDIM + coff) + g * 16);
            cp16(st + 2 * A_BYTES + B_BYTES + so,
                 (const char*)(Bl + (size_t)row * KDIM + coff) + g * 16);
        }
        cp_commit();
    };

    load_stage(0);
    load_stage(1);
    cp_wait<1>();
    __syncthreads();

    #pragma unroll 1
    for (int ch = 0; ch < NCHUNK; ++ch) {
        const uint32_t st = sbase + (uint32_t)(ch & 1) * STAGE_BYTES;
        const uint32_t aH = st;
        const uint32_t aL = st + A_BYTES;
        const uint32_t bH = st + 2 * A_BYTES;
        const uint32_t bL = st + 2 * A_BYTES + B_BYTES;

        #pragma unroll
        for (int ks = 0; ks < 2; ++ks) {
            uint32_t ahf[2][4], alf[2][4];
            #pragma unroll
            for (int mf = 0; mf < 2; ++mf) {
                int row = wm + mf * 16 + (lane & 15);
                int g   = ks * 2 + (lane >> 4);
                uint32_t so = swz_off(row, g);
                ldm_x4(ahf[mf][0], ahf[mf][1], ahf[mf][2], ahf[mf][3], aH + so);
                ldm_x4(alf[mf][0], alf[mf][1], alf[mf][2], alf[mf][3], aL + so);
            }
            uint32_t bhf[12][2], blf[12][2];
            #pragma unroll
            for (int p = 0; p < 6; ++p) {
                int row = wn + p * 16 + ((lane >> 4) << 3) + (lane & 7);
                int g   = ks * 2 + ((lane >> 3) & 1);
                uint32_t so = swz_off(row, g);
                ldm_x4(bhf[2 * p][0], bhf[2 * p][1], bhf[2 * p + 1][0], bhf[2 * p + 1][1],
                       bH + so);
                ldm_x4(blf[2 * p][0], blf[2 * p][1], blf[2 * p + 1][0], blf[2 * p + 1][1],
                       bL + so);
            }
            #pragma unroll
            for (int mf = 0; mf < 2; ++mf)
                #pragma unroll
                for (int nf = 0; nf < 12; ++nf) {
                    mma16816(c[mf][nf], ahf[mf], bhf[nf]);
                    mma16816(c[mf][nf], ahf[mf], blf[nf]);
                    mma16816(c[mf][nf], alf[mf], bhf[nf]);
                }
        }

        __syncthreads();
        if (ch + 2 < NCHUNK) {
            load_stage(ch + 2);
            cp_wait<1>();
        } else {
            cp_wait<0>();
        }
        __syncthreads();
    }

    // ---- epilogue: add bias, SCALAR stores (OUT=541 odd -> rows not 8B-aligned)
    const int mrow = lane >> 2;
    const int ncol = (lane & 3) * 2;
    #pragma unroll
    for (int mf = 0; mf < 2; ++mf) {
        #pragma unroll
        for (int half = 0; half < 2; ++half) {
            int m = bt + wm + mf * 16 + mrow + half * 8;
            float* orow = out + ((size_t)m * S + s) * OUT;
            #pragma unroll
            for (int nf = 0; nf < 12; ++nf) {
                int o = nt + wn + nf * 8 + ncol;
                if (o < OUT)     orow[o]     = c[mf][nf][2 * half + 0] + g_bias[s * OUT + o];
                if (o + 1 < OUT) orow[o + 1] = c[mf][nf][2 * half + 1] + g_bias[s * OUT + o + 1];
            }
        }
    }
}

// ============================================================================
extern "C" void kernel_launch(void* const* d_in, const int* in_sizes, int n_in,
                              void* d_out, int out_size)
{
    const float* x     = (const float*)d_in[0];
    const float* w1    = (const float*)d_in[1];
    const float* b1    = (const float*)d_in[2];
    const float* w2    = (const float*)d_in[3];
    const float* b2    = (const float*)d_in[4];
    const float* gamma = (const float*)d_in[5];
    const float* beta  = (const float*)d_in[6];
    const float* wl    = (const float*)d_in[7];
    const float* bl    = (const float*)d_in[8];
    float* out = (float*)d_out;

    cudaFuncSetAttribute(k6_gemm, cudaFuncAttributeMaxDynamicSharedMemorySize, DSMEM);

    k1_conv    <<<dim3(BATCH / 128, S), 128>>>(x, w1, b1, w2, b2);
    k2_stats   <<<dim3(KDIM, S), 256>>>();
    k3_finalize<<<1, 192>>>(gamma, beta);
    k_split    <<<dim3(KDIM / 64, BATCH / 32, S), 256>>>();
    k3_bsplit  <<<dim3(NPAD, S), KDIM>>>(wl);
    k3_bias    <<<dim3(OUT, S), KDIM>>>(wl, bl);
    k6_gemm    <<<dim3(NPAD / BN, BATCH / BM, S), 256, DSMEM>>>(out);
}

// round 6
// speedup vs baseline: 1.7827x; 1.0425x over previous
#include <cuda_runtime.h>
#include <cuda_bf16.h>
#include <math.h>
#include <stdint.h>

#define BATCH 32768
#define S 3
#define L 5
#define D1 32
#define D2 64
#define OUT 541
#define KDIM 320      // D2*L
#define NPAD 576      // padded N (3 x 192)
#define EPSBN 1e-5f

// GEMM tiling
#define BM 128
#define BN 192
#define BK 32
#define NCHUNK (KDIM / BK)      // 10
#define A_BYTES (BK * 256)      // 32 j-rows x 256B (128 b cols bf16) = 8192
#define B_BYTES (BN * 64)       // 12288
#define STAGE_BYTES (2 * A_BYTES + 2 * B_BYTES)  // 40960
#define DSMEM (2 * STAGE_BYTES) // 81920

// ---- device scratch (static: no allocations allowed) ----
__device__ __align__(16) __nv_bfloat16 g_ahi[(size_t)S * KDIM * BATCH];   // [s][j][b]
__device__ __align__(16) __nv_bfloat16 g_alo[(size_t)S * KDIM * BATCH];
__device__ __align__(16) __nv_bfloat16 g_bhi[(size_t)S * NPAD * KDIM];    // [s][o][j]
__device__ __align__(16) __nv_bfloat16 g_blo[(size_t)S * NPAD * KDIM];
__device__ float g_sum1[S * KDIM];
__device__ float g_sum2[S * KDIM];
__device__ float g_scale[S * D2];
__device__ float g_shift[S * D2];
__device__ float g_bias[S * OUT];

__device__ __forceinline__ float gelu_exact(float v) {
    return 0.5f * v * (1.0f + erff(v * 0.70710678118654752f));
}

// ---------------- portable PTX helpers (sm_80-era instructions only) --------
__device__ __forceinline__ uint32_t smem_u32(const void* p) {
    uint32_t a;
    asm("{ .reg .u64 t; cvta.to.shared.u64 t, %1; cvt.u32.u64 %0, t; }" : "=r"(a) : "l"(p));
    return a;
}
__device__ __forceinline__ void cp16(uint32_t dst, const void* src) {
    asm volatile("cp.async.cg.shared.global [%0], [%1], 16;" :: "r"(dst), "l"(src));
}
__device__ __forceinline__ void cp_commit() {
    asm volatile("cp.async.commit_group;" ::: "memory");
}
template<int N> __device__ __forceinline__ void cp_wait() {
    asm volatile("cp.async.wait_group %0;" :: "n"(N) : "memory");
}
__device__ __forceinline__ void ldm_x4(uint32_t& r0, uint32_t& r1, uint32_t& r2, uint32_t& r3,
                                       uint32_t addr) {
    asm volatile("ldmatrix.sync.aligned.m8n8.x4.shared.b16 {%0,%1,%2,%3}, [%4];"
                 : "=r"(r0), "=r"(r1), "=r"(r2), "=r"(r3) : "r"(addr));
}
__device__ __forceinline__ void ldm_x4_t(uint32_t& r0, uint32_t& r1, uint32_t& r2, uint32_t& r3,
                                         uint32_t addr) {
    asm volatile("ldmatrix.sync.aligned.m8n8.x4.trans.shared.b16 {%0,%1,%2,%3}, [%4];"
                 : "=r"(r0), "=r"(r1), "=r"(r2), "=r"(r3) : "r"(addr));
}
__device__ __forceinline__ void mma16816(float* c, const uint32_t* a, const uint32_t* b) {
    asm volatile(
        "mma.sync.aligned.m16n8k16.row.col.f32.bf16.bf16.f32 "
        "{%0,%1,%2,%3}, {%4,%5,%6,%7}, {%8,%9}, {%0,%1,%2,%3};"
        : "+f"(c[0]), "+f"(c[1]), "+f"(c[2]), "+f"(c[3])
        : "r"(a[0]), "r"(a[1]), "r"(a[2]), "r"(a[3]), "r"(b[0]), "r"(b[1]));
}
// B tile swizzle: 64B rows, 4 granules of 16B
__device__ __forceinline__ uint32_t swz_off(int row, int g) {
    return (uint32_t)(row * 64 + ((g ^ ((row >> 1) & 3)) << 4));
}
// A tile swizzle: 256B rows (128 bf16 b-cols), 16 granules of 16B
__device__ __forceinline__ uint32_t swzA(int row, int g) {
    return (uint32_t)(row * 256 + ((g ^ (row & 15)) << 4));
}

// ============================================================================
// K1: per (b,s) conv1 -> gelu -> conv2 -> gelu, write SPLIT bf16 hi/lo
//     directly to [s][j][b]  (A operand of the GEMM; BN folds into B side)
// ============================================================================
__global__ __launch_bounds__(128, 1) void k1_conv(
    const float* __restrict__ x,  const float* __restrict__ w1,
    const float* __restrict__ b1, const float* __restrict__ w2,
    const float* __restrict__ b2)
{
    __shared__ __align__(16) float w1s[D1 * 3];
    __shared__ float b1s[D1];
    __shared__ __align__(16) float w2s[3 * D2 * D1];
    __shared__ float b2s[D2];

    const int s = blockIdx.y;
    const int tid = threadIdx.x;

    for (int i = tid; i < D1 * 3; i += 128) w1s[i] = w1[s * D1 * 3 + i];
    for (int i = tid; i < D1; i += 128)     b1s[i] = b1[s * D1 + i];
    for (int i = tid; i < D2; i += 128)     b2s[i] = b2[s * D2 + i];
    for (int i = tid; i < 3 * D2 * D1; i += 128) {
        int d2 = i / (D1 * 3);
        int r  = i % (D1 * 3);
        int d1 = r / 3;
        int k  = r % 3;
        w2s[(k * D2 + d2) * D1 + d1] = w2[s * D2 * D1 * 3 + i];
    }
    __syncthreads();

    const int b = blockIdx.x * 128 + tid;

    float xp[L + 2];
    xp[0] = 0.0f; xp[L + 1] = 0.0f;
    #pragma unroll
    for (int l = 0; l < L; ++l) xp[l + 1] = x[(b * S + s) * L + l];

    float h1[L][D1];
    #pragma unroll
    for (int l = 0; l < L; ++l) {
        #pragma unroll
        for (int d1 = 0; d1 < D1; ++d1) {
            float v = b1s[d1]
                    + w1s[d1 * 3 + 0] * xp[l]
                    + w1s[d1 * 3 + 1] * xp[l + 1]
                    + w1s[d1 * 3 + 2] * xp[l + 2];
            h1[l][d1] = gelu_exact(v);
        }
    }

    __nv_bfloat16* outHi = &g_ahi[(size_t)s * KDIM * BATCH + b];
    __nv_bfloat16* outLo = &g_alo[(size_t)s * KDIM * BATCH + b];
    for (int d2 = 0; d2 < D2; ++d2) {
        float acc[L];
        #pragma unroll
        for (int l = 0; l < L; ++l) acc[l] = b2s[d2];
        #pragma unroll
        for (int k = 0; k < 3; ++k) {
            const float4* wp = (const float4*)&w2s[(k * D2 + d2) * D1];
            #pragma unroll
            for (int q = 0; q < D1 / 4; ++q) {
                float4 w = wp[q];
                #pragma unroll
                for (int l = 0; l < L; ++l) {
                    int c = l + k - 1;
                    if (c >= 0 && c < L) {
                        acc[l] += w.x * h1[c][q * 4 + 0] + w.y * h1[c][q * 4 + 1]
                                + w.z * h1[c][q * 4 + 2] + w.w * h1[c][q * 4 + 3];
                    }
                }
            }
        }
        #pragma unroll
        for (int l = 0; l < L; ++l) {
            float v = gelu_exact(acc[l]);
            __nv_bfloat16 hi = __float2bfloat16(v);
            __nv_bfloat16 lo = __float2bfloat16(v - __bfloat162float(hi));
            size_t off = (size_t)(d2 * L + l) * BATCH;
            outHi[off] = hi;     // coalesced over b
            outLo[off] = lo;
        }
    }
}

// ============================================================================
// K2: per (s,j) sum / sumsq over b (reconstruct v = hi + lo, err ~2^-16)
// ============================================================================
__global__ void k2_stats()
{
    const int j = blockIdx.x, s = blockIdx.y, tid = threadIdx.x;
    const __nv_bfloat16* ph = &g_ahi[(size_t)(s * KDIM + j) * BATCH];
    const __nv_bfloat16* pl = &g_alo[(size_t)(s * KDIM + j) * BATCH];
    float s1 = 0.0f, s2 = 0.0f;
    for (int i = tid; i < BATCH; i += 256) {
        float v = __bfloat162float(ph[i]) + __bfloat162float(pl[i]);
        s1 += v;
        s2 += v * v;
    }
    __shared__ float r1[256], r2[256];
    r1[tid] = s1; r2[tid] = s2;
    __syncthreads();
    for (int off = 128; off > 0; off >>= 1) {
        if (tid < off) { r1[tid] += r1[tid + off]; r2[tid] += r2[tid + off]; }
        __syncthreads();
    }
    if (tid == 0) {
        g_sum1[s * KDIM + j] = r1[0];
        g_sum2[s * KDIM + j] = r2[0];
    }
}

// ============================================================================
// K3a: BN finalize
// ============================================================================
__global__ void k3_finalize(const float* __restrict__ gamma, const float* __restrict__ beta)
{
    int t = threadIdx.x;
    if (t >= S * D2) return;
    int s = t / D2, d2 = t % D2;
    float S1 = 0.0f, S2 = 0.0f;
    #pragma unroll
    for (int l = 0; l < L; ++l) {
        S1 += g_sum1[s * KDIM + d2 * L + l];
        S2 += g_sum2[s * KDIM + d2 * L + l];
    }
    const float invn = 1.0f / (float)(BATCH * L);
    float mean = S1 * invn;
    float var  = S2 * invn - mean * mean;
    float inv  = rsqrtf(var + EPSBN);
    float sc   = gamma[t] * inv;
    g_scale[t] = sc;
    g_shift[t] = beta[t] - mean * sc;
}

// ============================================================================
// K3b: scale-folded, transposed, split weights -> bf16 hi/lo [s][o][j]
// ============================================================================
__global__ void k3_bsplit(const float* __restrict__ wl)
{
    int o = blockIdx.x, s = blockIdx.y, j = threadIdx.x;  // 320 threads
    float v = 0.0f;
    if (o < OUT) v = wl[((size_t)s * OUT + o) * KDIM + j] * g_scale[s * D2 + j / L];
    __nv_bfloat16 hi = __float2bfloat16(v);
    __nv_bfloat16 lo = __float2bfloat16(v - __bfloat162float(hi));
    size_t base = ((size_t)(s * NPAD + o)) * KDIM + j;
    g_bhi[base] = hi;
    g_blo[base] = lo;
}

// ============================================================================
// K3c: effective bias
// ============================================================================
__global__ void k3_bias(const float* __restrict__ wl, const float* __restrict__ bl)
{
    int o = blockIdx.x, s = blockIdx.y, j = threadIdx.x;  // 320 threads
    float v = wl[((size_t)s * OUT + o) * KDIM + j] * g_shift[s * D2 + j / L];
    __shared__ float red[KDIM];
    red[j] = v;
    __syncthreads();
    if (j < 64)  red[j] += red[j + 256];
    __syncthreads();
    if (j < 128) red[j] += red[j + 128];
    __syncthreads();
    if (j < 64)  red[j] += red[j + 64];
    __syncthreads();
    if (j < 32) {
        float xv = red[j] + red[j + 32];
        #pragma unroll
        for (int off = 16; off > 0; off >>= 1)
            xv += __shfl_down_sync(0xffffffffu, xv, off);
        if (j == 0) g_bias[s * OUT + o] = bl[s * OUT + o] + xv;
    }
}

// ============================================================================
// K6: HMMA split-GEMM.  out = Ahi*Bhi + Ahi*Blo + Alo*Bhi (+bias)
//   A stored M-major [j][b]  -> ldmatrix.trans fragments
//   B stored K-major [o][j]  -> ldmatrix fragments
// ============================================================================
__global__ __launch_bounds__(256, 1) void k6_gemm(float* __restrict__ out)
{
    extern __shared__ __align__(16) char dyn[];
    const uint32_t sbase = smem_u32(dyn);

    const int tid  = threadIdx.x;
    const int wid  = tid >> 5;
    const int lane = tid & 31;
    const int nt = blockIdx.x * BN;   // 0,192,384 (fastest -> A L2 reuse)
    const int bt = blockIdx.y * BM;
    const int s  = blockIdx.z;

    const int wm = (wid & 3) * 32;    // warp m offset
    const int wn = (wid >> 2) * 96;   // warp n offset

    const __nv_bfloat16* Ah = g_ahi + (size_t)s * KDIM * BATCH + bt;   // + j*BATCH
    const __nv_bfloat16* Al = g_alo + (size_t)s * KDIM * BATCH + bt;
    const __nv_bfloat16* Bh = g_bhi + ((size_t)(s * NPAD + nt)) * KDIM;
    const __nv_bfloat16* Bl = g_blo + ((size_t)(s * NPAD + nt)) * KDIM;

    float c[2][12][4];
    #pragma unroll
    for (int i = 0; i < 2; ++i)
        #pragma unroll
        for (int j = 0; j < 12; ++j)
            #pragma unroll
            for (int k = 0; k < 4; ++k) c[i][j][k] = 0.0f;

    auto load_stage = [&](int chunk) {
        const uint32_t st = sbase + (uint32_t)(chunk & 1) * STAGE_BYTES;
        const int coff = chunk * BK;
        // A hi/lo: 32 j-rows x 16 granules of 16B (8 b's each)
        #pragma unroll
        for (int u = tid; u < BK * 16; u += 256) {
            int row = u >> 4, g = u & 15;
            uint32_t so = swzA(row, g);
            const __nv_bfloat16* pa = Ah + (size_t)(coff + row) * BATCH + g * 8;
            const __nv_bfloat16* qa = Al + (size_t)(coff + row) * BATCH + g * 8;
            cp16(st + so, pa);
            cp16(st + A_BYTES + so, qa);
        }
        // B hi/lo: 192 o-rows x 4 granules
        #pragma unroll
        for (int u = tid; u < BN * 4; u += 256) {
            int row = u >> 2, g = u & 3;
            uint32_t so = swz_off(row, g);
            cp16(st + 2 * A_BYTES + so,
                 (const char*)(Bh + (size_t)row * KDIM + coff) + g * 16);
            cp16(st + 2 * A_BYTES + B_BYTES + so,
                 (const char*)(Bl + (size_t)row * KDIM + coff) + g * 16);
        }
        cp_commit();
    };

    load_stage(0);
    load_stage(1);
    cp_wait<1>();
    __syncthreads();

    #pragma unroll 1
    for (int ch = 0; ch < NCHUNK; ++ch) {
        const uint32_t st = sbase + (uint32_t)(ch & 1) * STAGE_BYTES;
        const uint32_t aH = st;
        const uint32_t aL = st + A_BYTES;
        const uint32_t bH = st + 2 * A_BYTES;
        const uint32_t bL = st + 2 * A_BYTES + B_BYTES;

        #pragma unroll
        for (int ks = 0; ks < 2; ++ks) {
            // A fragments via ldmatrix.trans from M-major tile
            // lane -> (j-row, b-granule): matrices (m0k0),(m8k0),(m0k8),(m8k8)
            uint32_t ahf[2][4], alf[2][4];
            #pragma unroll
            for (int mf = 0; mf < 2; ++mf) {
                int jr = ks * 16 + ((lane >> 4) << 3) + (lane & 7);
                int g  = (wm + mf * 16) / 8 + ((lane >> 3) & 1);
                uint32_t so = swzA(jr, g);
                ldm_x4_t(ahf[mf][0], ahf[mf][1], ahf[mf][2], ahf[mf][3], aH + so);
                ldm_x4_t(alf[mf][0], alf[mf][1], alf[mf][2], alf[mf][3], aL + so);
            }
            // B fragments (unchanged, K-major)
            uint32_t bhf[12][2], blf[12][2];
            #pragma unroll
            for (int p = 0; p < 6; ++p) {
                int row = wn + p * 16 + ((lane >> 4) << 3) + (lane & 7);
                int g   = ks * 2 + ((lane >> 3) & 1);
                uint32_t so = swz_off(row, g);
                ldm_x4(bhf[2 * p][0], bhf[2 * p][1], bhf[2 * p + 1][0], bhf[2 * p + 1][1],
                       bH + so);
                ldm_x4(blf[2 * p][0], blf[2 * p][1], blf[2 * p + 1][0], blf[2 * p + 1][1],
                       bL + so);
            }
            #pragma unroll
            for (int mf = 0; mf < 2; ++mf)
                #pragma unroll
                for (int nf = 0; nf < 12; ++nf) {
                    mma16816(c[mf][nf], ahf[mf], bhf[nf]);
                    mma16816(c[mf][nf], ahf[mf], blf[nf]);
                    mma16816(c[mf][nf], alf[mf], bhf[nf]);
                }
        }

        __syncthreads();
        if (ch + 2 < NCHUNK) {
            load_stage(ch + 2);
            cp_wait<1>();
        } else {
            cp_wait<0>();
        }
        __syncthreads();
    }

    // ---- epilogue: add bias, SCALAR stores (OUT=541 odd -> rows not 8B-aligned)
    const int mrow = lane >> 2;
    const int ncol = (lane & 3) * 2;
    #pragma unroll
    for (int mf = 0; mf < 2; ++mf) {
        #pragma unroll
        for (int half = 0; half < 2; ++half) {
            int m = bt + wm + mf * 16 + mrow + half * 8;
            float* orow = out + ((size_t)m * S + s) * OUT;
            #pragma unroll
            for (int nf = 0; nf < 12; ++nf) {
                int o = nt + wn + nf * 8 + ncol;
                if (o < OUT)     orow[o]     = c[mf][nf][2 * half + 0] + g_bias[s * OUT + o];
                if (o + 1 < OUT) orow[o + 1] = c[mf][nf][2 * half + 1] + g_bias[s * OUT + o + 1];
            }
        }
    }
}

// ============================================================================
extern "C" void kernel_launch(void* const* d_in, const int* in_sizes, int n_in,
                              void* d_out, int out_size)
{
    const float* x     = (const float*)d_in[0];
    const float* w1    = (const float*)d_in[1];
    const float* b1    = (const float*)d_in[2];
    const float* w2    = (const float*)d_in[3];
    const float* b2    = (const float*)d_in[4];
    const float* gamma = (const float*)d_in[5];
    const float* beta  = (const float*)d_in[6];
    const float* wl    = (const float*)d_in[7];
    const float* bl    = (const float*)d_in[8];
    float* out = (float*)d_out;

    cudaFuncSetAttribute(k6_gemm, cudaFuncAttributeMaxDynamicSharedMemorySize, DSMEM);

    k1_conv    <<<dim3(BATCH / 128, S), 128>>>(x, w1, b1, w2, b2);
    k2_stats   <<<dim3(KDIM, S), 256>>>();
    k3_finalize<<<1, 192>>>(gamma, beta);
    k3_bsplit  <<<dim3(NPAD, S), KDIM>>>(wl);
    k3_bias    <<<dim3(OUT, S), KDIM>>>(wl, bl);
    k6_gemm    <<<dim3(NPAD / BN, BATCH / BM, S), 256, DSMEM>>>(out);
}

// round 7
// speedup vs baseline: 1.8624x; 1.0447x over previous
#include <cuda_runtime.h>
#include <cuda_bf16.h>
#include <math.h>
#include <stdint.h>

#define BATCH 32768
#define S 3
#define L 5
#define D1 32
#define D2 64
#define OUT 541
#define KDIM 320      // D2*L
#define NPAD 576      // padded N (3 x 192)
#define EPSBN 1e-5f

// GEMM tiling
#define BM 128
#define BN 192
#define BK 32
#define NCHUNK (KDIM / BK)      // 10
#define NSTAGE 4
#define A_BYTES (BK * 256)      // 32 j-rows x 256B (128 b cols bf16) = 8192
#define B_BYTES (BN * 64)       // 12288
#define STAGE_BYTES (2 * A_BYTES + 2 * B_BYTES)  // 40960
#define DSMEM (NSTAGE * STAGE_BYTES)             // 163840

// ---- device scratch (static: no allocations allowed) ----
__device__ __align__(16) __nv_bfloat16 g_ahi[(size_t)S * KDIM * BATCH];   // [s][j][b]
__device__ __align__(16) __nv_bfloat16 g_alo[(size_t)S * KDIM * BATCH];
__device__ __align__(16) __nv_bfloat16 g_bhi[(size_t)S * NPAD * KDIM];    // [s][o][j]
__device__ __align__(16) __nv_bfloat16 g_blo[(size_t)S * NPAD * KDIM];
__device__ float g_sum1[S * KDIM];
__device__ float g_sum2[S * KDIM];
__device__ float g_bias[S * OUT];

__device__ __forceinline__ float gelu_exact(float v) {
    return 0.5f * v * (1.0f + erff(v * 0.70710678118654752f));
}

// ---------------- portable PTX helpers (sm_80-era instructions only) --------
__device__ __forceinline__ uint32_t smem_u32(const void* p) {
    uint32_t a;
    asm("{ .reg .u64 t; cvta.to.shared.u64 t, %1; cvt.u32.u64 %0, t; }" : "=r"(a) : "l"(p));
    return a;
}
__device__ __forceinline__ void cp16(uint32_t dst, const void* src) {
    asm volatile("cp.async.cg.shared.global [%0], [%1], 16;" :: "r"(dst), "l"(src));
}
__device__ __forceinline__ void cp_commit() {
    asm volatile("cp.async.commit_group;" ::: "memory");
}
template<int N> __device__ __forceinline__ void cp_wait() {
    asm volatile("cp.async.wait_group %0;" :: "n"(N) : "memory");
}
__device__ __forceinline__ void ldm_x4(uint32_t& r0, uint32_t& r1, uint32_t& r2, uint32_t& r3,
                                       uint32_t addr) {
    asm volatile("ldmatrix.sync.aligned.m8n8.x4.shared.b16 {%0,%1,%2,%3}, [%4];"
                 : "=r"(r0), "=r"(r1), "=r"(r2), "=r"(r3) : "r"(addr));
}
__device__ __forceinline__ void ldm_x4_t(uint32_t& r0, uint32_t& r1, uint32_t& r2, uint32_t& r3,
                                         uint32_t addr) {
    asm volatile("ldmatrix.sync.aligned.m8n8.x4.trans.shared.b16 {%0,%1,%2,%3}, [%4];"
                 : "=r"(r0), "=r"(r1), "=r"(r2), "=r"(r3) : "r"(addr));
}
__device__ __forceinline__ void mma16816(float* c, const uint32_t* a, const uint32_t* b) {
    asm volatile(
        "mma.sync.aligned.m16n8k16.row.col.f32.bf16.bf16.f32 "
        "{%0,%1,%2,%3}, {%4,%5,%6,%7}, {%8,%9}, {%0,%1,%2,%3};"
        : "+f"(c[0]), "+f"(c[1]), "+f"(c[2]), "+f"(c[3])
        : "r"(a[0]), "r"(a[1]), "r"(a[2]), "r"(a[3]), "r"(b[0]), "r"(b[1]));
}
// B tile swizzle: 64B rows, 4 granules of 16B
__device__ __forceinline__ uint32_t swz_off(int row, int g) {
    return (uint32_t)(row * 64 + ((g ^ ((row >> 1) & 3)) << 4));
}
// A tile swizzle: 256B rows (128 bf16 b-cols), 16 granules of 16B
__device__ __forceinline__ uint32_t swzA(int row, int g) {
    return (uint32_t)(row * 256 + ((g ^ (row & 15)) << 4));
}

// ============================================================================
// K1: per (b,s) conv1 -> gelu -> conv2 -> gelu, write SPLIT bf16 hi/lo
//     directly to [s][j][b]  (A operand of the GEMM; BN folds into B side)
// ============================================================================
__global__ __launch_bounds__(128, 1) void k1_conv(
    const float* __restrict__ x,  const float* __restrict__ w1,
    const float* __restrict__ b1, const float* __restrict__ w2,
    const float* __restrict__ b2)
{
    __shared__ __align__(16) float w1s[D1 * 3];
    __shared__ float b1s[D1];
    __shared__ __align__(16) float w2s[3 * D2 * D1];
    __shared__ float b2s[D2];

    const int s = blockIdx.y;
    const int tid = threadIdx.x;

    for (int i = tid; i < D1 * 3; i += 128) w1s[i] = w1[s * D1 * 3 + i];
    for (int i = tid; i < D1; i += 128)     b1s[i] = b1[s * D1 + i];
    for (int i = tid; i < D2; i += 128)     b2s[i] = b2[s * D2 + i];
    for (int i = tid; i < 3 * D2 * D1; i += 128) {
        int d2 = i / (D1 * 3);
        int r  = i % (D1 * 3);
        int d1 = r / 3;
        int k  = r % 3;
        w2s[(k * D2 + d2) * D1 + d1] = w2[s * D2 * D1 * 3 + i];
    }
    __syncthreads();

    const int b = blockIdx.x * 128 + tid;

    float xp[L + 2];
    xp[0] = 0.0f; xp[L + 1] = 0.0f;
    #pragma unroll
    for (int l = 0; l < L; ++l) xp[l + 1] = x[(b * S + s) * L + l];

    float h1[L][D1];
    #pragma unroll
    for (int l = 0; l < L; ++l) {
        #pragma unroll
        for (int d1 = 0; d1 < D1; ++d1) {
            float v = b1s[d1]
                    + w1s[d1 * 3 + 0] * xp[l]
                    + w1s[d1 * 3 + 1] * xp[l + 1]
                    + w1s[d1 * 3 + 2] * xp[l + 2];
            h1[l][d1] = gelu_exact(v);
        }
    }

    __nv_bfloat16* outHi = &g_ahi[(size_t)s * KDIM * BATCH + b];
    __nv_bfloat16* outLo = &g_alo[(size_t)s * KDIM * BATCH + b];
    for (int d2 = 0; d2 < D2; ++d2) {
        float acc[L];
        #pragma unroll
        for (int l = 0; l < L; ++l) acc[l] = b2s[d2];
        #pragma unroll
        for (int k = 0; k < 3; ++k) {
            const float4* wp = (const float4*)&w2s[(k * D2 + d2) * D1];
            #pragma unroll
            for (int q = 0; q < D1 / 4; ++q) {
                float4 w = wp[q];
                #pragma unroll
                for (int l = 0; l < L; ++l) {
                    int c = l + k - 1;
                    if (c >= 0 && c < L) {
                        acc[l] += w.x * h1[c][q * 4 + 0] + w.y * h1[c][q * 4 + 1]
                                + w.z * h1[c][q * 4 + 2] + w.w * h1[c][q * 4 + 3];
                    }
                }
            }
        }
        #pragma unroll
        for (int l = 0; l < L; ++l) {
            float v = gelu_exact(acc[l]);
            __nv_bfloat16 hi = __float2bfloat16(v);
            __nv_bfloat16 lo = __float2bfloat16(v - __bfloat162float(hi));
            size_t off = (size_t)(d2 * L + l) * BATCH;
            outHi[off] = hi;     // coalesced over b
            outLo[off] = lo;
        }
    }
}

// ============================================================================
// K2: per (s,j) sum / sumsq over b (reconstruct v = hi + lo, err ~2^-16)
// ============================================================================
__global__ void k2_stats()
{
    const int j = blockIdx.x, s = blockIdx.y, tid = threadIdx.x;
    const __nv_bfloat16* ph = &g_ahi[(size_t)(s * KDIM + j) * BATCH];
    const __nv_bfloat16* pl = &g_alo[(size_t)(s * KDIM + j) * BATCH];
    float s1 = 0.0f, s2 = 0.0f;
    for (int i = tid; i < BATCH; i += 256) {
        float v = __bfloat162float(ph[i]) + __bfloat162float(pl[i]);
        s1 += v;
        s2 += v * v;
    }
    __shared__ float r1[256], r2[256];
    r1[tid] = s1; r2[tid] = s2;
    __syncthreads();
    for (int off = 128; off > 0; off >>= 1) {
        if (tid < off) { r1[tid] += r1[tid + off]; r2[tid] += r2[tid + off]; }
        __syncthreads();
    }
    if (tid == 0) {
        g_sum1[s * KDIM + j] = r1[0];
        g_sum2[s * KDIM + j] = r2[0];
    }
}

// ============================================================================
// K3all: fused BN-finalize + weight split + bias.  Each block recomputes the
//   64 (scale, shift) pairs from g_sum1/2 (trivial), so no kernel ordering
//   dependency.  bid < NPAD: produce B hi/lo row o=bid.  Else: bias row.
// ============================================================================
__global__ __launch_bounds__(KDIM) void k3_all(
    const float* __restrict__ gamma, const float* __restrict__ beta,
    const float* __restrict__ wl,    const float* __restrict__ bl)
{
    const int bid = blockIdx.x, s = blockIdx.y, j = threadIdx.x;  // 320 threads
    __shared__ float sc_s[D2], sh_s[D2];
    if (j < D2) {
        float S1 = 0.0f, S2 = 0.0f;
        #pragma unroll
        for (int l = 0; l < L; ++l) {
            S1 += g_sum1[s * KDIM + j * L + l];
            S2 += g_sum2[s * KDIM + j * L + l];
        }
        const float invn = 1.0f / (float)(BATCH * L);
        float mean = S1 * invn;
        float var  = S2 * invn - mean * mean;
        float inv  = rsqrtf(var + EPSBN);
        float sc   = gamma[s * D2 + j] * inv;
        sc_s[j] = sc;
        sh_s[j] = beta[s * D2 + j] - mean * sc;
    }
    __syncthreads();

    if (bid < NPAD) {
        // weight split: g_bhi/g_blo[s][o][j] = wl[o][j] * scale[j/L]  (o>=OUT: 0)
        const int o = bid;
        float v = 0.0f;
        if (o < OUT) v = wl[((size_t)s * OUT + o) * KDIM + j] * sc_s[j / L];
        __nv_bfloat16 hi = __float2bfloat16(v);
        __nv_bfloat16 lo = __float2bfloat16(v - __bfloat162float(hi));
        size_t base = ((size_t)(s * NPAD + o)) * KDIM + j;
        g_bhi[base] = hi;
        g_blo[base] = lo;
    } else {
        // effective bias: g_bias[s][o] = bl + sum_j wl[o][j] * shift[j/L]
        const int o = bid - NPAD;   // < OUT
        float v = wl[((size_t)s * OUT + o) * KDIM + j] * sh_s[j / L];
        __shared__ float red[KDIM];
        red[j] = v;
        __syncthreads();
        if (j < 64)  red[j] += red[j + 256];
        __syncthreads();
        if (j < 128) red[j] += red[j + 128];
        __syncthreads();
        if (j < 64)  red[j] += red[j + 64];
        __syncthreads();
        if (j < 32) {
            float xv = red[j] + red[j + 32];
            #pragma unroll
            for (int off = 16; off > 0; off >>= 1)
                xv += __shfl_down_sync(0xffffffffu, xv, off);
            if (j == 0) g_bias[s * OUT + o] = bl[s * OUT + o] + xv;
        }
    }
}

// ============================================================================
// K6: HMMA split-GEMM.  out = Ahi*Bhi + Ahi*Blo + Alo*Bhi (+bias)
//   4-stage cp.async pipeline, ONE __syncthreads per K-chunk.
// ============================================================================
__global__ __launch_bounds__(256, 1) void k6_gemm(float* __restrict__ out)
{
    extern __shared__ __align__(16) char dyn[];
    const uint32_t sbase = smem_u32(dyn);

    const int tid  = threadIdx.x;
    const int wid  = tid >> 5;
    const int lane = tid & 31;
    const int nt = blockIdx.x * BN;   // 0,192,384 (fastest -> A L2 reuse)
    const int bt = blockIdx.y * BM;
    const int s  = blockIdx.z;

    const int wm = (wid & 3) * 32;    // warp m offset
    const int wn = (wid >> 2) * 96;   // warp n offset

    const __nv_bfloat16* Ah = g_ahi + (size_t)s * KDIM * BATCH + bt;   // + j*BATCH
    const __nv_bfloat16* Al = g_alo + (size_t)s * KDIM * BATCH + bt;
    const __nv_bfloat16* Bh = g_bhi + ((size_t)(s * NPAD + nt)) * KDIM;
    const __nv_bfloat16* Bl = g_blo + ((size_t)(s * NPAD + nt)) * KDIM;

    float c[2][12][4];
    #pragma unroll
    for (int i = 0; i < 2; ++i)
        #pragma unroll
        for (int j = 0; j < 12; ++j)
            #pragma unroll
            for (int k = 0; k < 4; ++k) c[i][j][k] = 0.0f;

    auto load_stage = [&](int chunk) {
        const uint32_t st = sbase + (uint32_t)(chunk & (NSTAGE - 1)) * STAGE_BYTES;
        const int coff = chunk * BK;
        // A hi/lo: 32 j-rows x 16 granules of 16B (8 b's each)
        #pragma unroll
        for (int u = tid; u < BK * 16; u += 256) {
            int row = u >> 4, g = u & 15;
            uint32_t so = swzA(row, g);
            cp16(st + so,           Ah + (size_t)(coff + row) * BATCH + g * 8);
            cp16(st + A_BYTES + so, Al + (size_t)(coff + row) * BATCH + g * 8);
        }
        // B hi/lo: 192 o-rows x 4 granules
        #pragma unroll
        for (int u = tid; u < BN * 4; u += 256) {
            int row = u >> 2, g = u & 3;
            uint32_t so = swz_off(row, g);
            cp16(st + 2 * A_BYTES + so,
                 (const char*)(Bh + (size_t)row * KDIM + coff) + g * 16);
            cp16(st + 2 * A_BYTES + B_BYTES + so,
                 (const char*)(Bl + (size_t)row * KDIM + coff) + g * 16);
        }
        cp_commit();
    };

    load_stage(0);
    load_stage(1);
    load_stage(2);

    #pragma unroll 1
    for (int ch = 0; ch < NCHUNK; ++ch) {
        cp_wait<2>();          // stage ch landed (<=2 younger groups in flight)
        __syncthreads();       // all threads see it; prev stage fully consumed

        const uint32_t st = sbase + (uint32_t)(ch & (NSTAGE - 1)) * STAGE_BYTES;
        const uint32_t aH = st;
        const uint32_t aL = st + A_BYTES;
        const uint32_t bH = st + 2 * A_BYTES;
        const uint32_t bL = st + 2 * A_BYTES + B_BYTES;

        #pragma unroll
        for (int ks = 0; ks < 2; ++ks) {
            uint32_t ahf[2][4], alf[2][4];
            #pragma unroll
            for (int mf = 0; mf < 2; ++mf) {
                int jr = ks * 16 + ((lane >> 4) << 3) + (lane & 7);
                int g  = (wm + mf * 16) / 8 + ((lane >> 3) & 1);
                uint32_t so = swzA(jr, g);
                ldm_x4_t(ahf[mf][0], ahf[mf][1], ahf[mf][2], ahf[mf][3], aH + so);
                ldm_x4_t(alf[mf][0], alf[mf][1], alf[mf][2], alf[mf][3], aL + so);
            }
            uint32_t bhf[12][2], blf[12][2];
            #pragma unroll
            for (int p = 0; p < 6; ++p) {
                int row = wn + p * 16 + ((lane >> 4) << 3) + (lane & 7);
                int g   = ks * 2 + ((lane >> 3) & 1);
                uint32_t so = swz_off(row, g);
                ldm_x4(bhf[2 * p][0], bhf[2 * p][1], bhf[2 * p + 1][0], bhf[2 * p + 1][1],
                       bH + so);
                ldm_x4(blf[2 * p][0], blf[2 * p][1], blf[2 * p + 1][0], blf[2 * p + 1][1],
                       bL + so);
            }
            #pragma unroll
            for (int mf = 0; mf < 2; ++mf)
                #pragma unroll
                for (int nf = 0; nf < 12; ++nf) {
                    mma16816(c[mf][nf], ahf[mf], bhf[nf]);
                    mma16816(c[mf][nf], ahf[mf], blf[nf]);
                    mma16816(c[mf][nf], alf[mf], bhf[nf]);
                }
        }

        if (ch + 3 < NCHUNK) load_stage(ch + 3);   // overwrites buffer read at ch-1
    }

    // ---- epilogue: add bias, SCALAR stores (OUT=541 odd -> rows not 8B-aligned)
    const int mrow = lane >> 2;
    const int ncol = (lane & 3) * 2;
    #pragma unroll
    for (int mf = 0; mf < 2; ++mf) {
        #pragma unroll
        for (int half = 0; half < 2; ++half) {
            int m = bt + wm + mf * 16 + mrow + half * 8;
            float* orow = out + ((size_t)m * S + s) * OUT;
            #pragma unroll
            for (int nf = 0; nf < 12; ++nf) {
                int o = nt + wn + nf * 8 + ncol;
                if (o < OUT)     orow[o]     = c[mf][nf][2 * half + 0] + g_bias[s * OUT + o];
                if (o + 1 < OUT) orow[o + 1] = c[mf][nf][2 * half + 1] + g_bias[s * OUT + o + 1];
            }
        }
    }
}

// ============================================================================
extern "C" void kernel_launch(void* const* d_in, const int* in_sizes, int n_in,
                              void* d_out, int out_size)
{
    const float* x     = (const float*)d_in[0];
    const float* w1    = (const float*)d_in[1];
    const float* b1    = (const float*)d_in[2];
    const float* w2    = (const float*)d_in[3];
    const float* b2    = (const float*)d_in[4];
    const float* gamma = (const float*)d_in[5];
    const float* beta  = (const float*)d_in[6];
    const float* wl    = (const float*)d_in[7];
    const float* bl    = (const float*)d_in[8];
    float* out = (float*)d_out;

    cudaFuncSetAttribute(k6_gemm, cudaFuncAttributeMaxDynamicSharedMemorySize, DSMEM);

    k1_conv <<<dim3(BATCH / 128, S), 128>>>(x, w1, b1, w2, b2);
    k2_stats<<<dim3(KDIM, S), 256>>>();
    k3_all  <<<dim3(NPAD + OUT, S), KDIM>>>(gamma, beta, wl, bl);
    k6_gemm <<<dim3(NPAD / BN, BATCH / BM, S), 256, DSMEM>>>(out);
}

// round 8
// speedup vs baseline: 1.8651x; 1.0015x over previous
#include <cuda_runtime.h>
#include <cuda_bf16.h>
#include <math.h>
#include <stdint.h>

#define BATCH 32768
#define S 3
#define L 5
#define D1 32
#define D2 64
#define OUT 541
#define KDIM 320      // D2*L
#define NPAD 576      // padded N (3 x 192)
#define EPSBN 1e-5f

// GEMM tiling
#define BM 128
#define BN 192
#define BK 32
#define NCHUNK (KDIM / BK)      // 10
#define NSTAGE 4
#define A_BYTES (BK * 256)      // 32 j-rows x 256B (128 b cols bf16) = 8192
#define B_BYTES (BN * 64)       // 12288
#define STAGE_BYTES (2 * A_BYTES + 2 * B_BYTES)  // 40960
#define DSMEM (NSTAGE * STAGE_BYTES)             // 163840

// ---- device scratch (static: no allocations allowed) ----
__device__ __align__(16) __nv_bfloat16 g_ahi[(size_t)S * KDIM * BATCH];   // [s][j][b]
__device__ __align__(16) __nv_bfloat16 g_alo[(size_t)S * KDIM * BATCH];
__device__ __align__(16) __nv_bfloat16 g_bhi[(size_t)S * NPAD * KDIM];    // [s][o][j]
__device__ __align__(16) __nv_bfloat16 g_blo[(size_t)S * NPAD * KDIM];
__device__ float g_sum1[S * KDIM];
__device__ float g_sum2[S * KDIM];
__device__ float g_bias[S * OUT];

__device__ __forceinline__ float gelu_exact(float v) {
    return 0.5f * v * (1.0f + erff(v * 0.70710678118654752f));
}

// ---------------- portable PTX helpers (sm_80-era instructions only) --------
__device__ __forceinline__ uint32_t smem_u32(const void* p) {
    uint32_t a;
    asm("{ .reg .u64 t; cvta.to.shared.u64 t, %1; cvt.u32.u64 %0, t; }" : "=r"(a) : "l"(p));
    return a;
}
__device__ __forceinline__ void cp16(uint32_t dst, const void* src) {
    asm volatile("cp.async.cg.shared.global [%0], [%1], 16;" :: "r"(dst), "l"(src));
}
__device__ __forceinline__ void cp_commit() {
    asm volatile("cp.async.commit_group;" ::: "memory");
}
template<int N> __device__ __forceinline__ void cp_wait() {
    asm volatile("cp.async.wait_group %0;" :: "n"(N) : "memory");
}
__device__ __forceinline__ void ldm_x4(uint32_t& r0, uint32_t& r1, uint32_t& r2, uint32_t& r3,
                                       uint32_t addr) {
    asm volatile("ldmatrix.sync.aligned.m8n8.x4.shared.b16 {%0,%1,%2,%3}, [%4];"
                 : "=r"(r0), "=r"(r1), "=r"(r2), "=r"(r3) : "r"(addr));
}
__device__ __forceinline__ void ldm_x4_t(uint32_t& r0, uint32_t& r1, uint32_t& r2, uint32_t& r3,
                                         uint32_t addr) {
    asm volatile("ldmatrix.sync.aligned.m8n8.x4.trans.shared.b16 {%0,%1,%2,%3}, [%4];"
                 : "=r"(r0), "=r"(r1), "=r"(r2), "=r"(r3) : "r"(addr));
}
__device__ __forceinline__ void mma16816(float* c, const uint32_t* a, const uint32_t* b) {
    asm volatile(
        "mma.sync.aligned.m16n8k16.row.col.f32.bf16.bf16.f32 "
        "{%0,%1,%2,%3}, {%4,%5,%6,%7}, {%8,%9}, {%0,%1,%2,%3};"
        : "+f"(c[0]), "+f"(c[1]), "+f"(c[2]), "+f"(c[3])
        : "r"(a[0]), "r"(a[1]), "r"(a[2]), "r"(a[3]), "r"(b[0]), "r"(b[1]));
}
// B tile swizzle: 64B rows, 4 granules of 16B
__device__ __forceinline__ uint32_t swz_off(int row, int g) {
    return (uint32_t)(row * 64 + ((g ^ ((row >> 1) & 3)) << 4));
}
// A tile swizzle: 256B rows (128 bf16 b-cols), 16 granules of 16B
__device__ __forceinline__ uint32_t swzA(int row, int g) {
    return (uint32_t)(row * 256 + ((g ^ (row & 15)) << 4));
}

// ============================================================================
// K1: per (b,s) conv1 -> gelu -> conv2 -> gelu, write SPLIT bf16 hi/lo
//     directly to [s][j][b]  (A operand of the GEMM; BN folds into B side)
// ============================================================================
__global__ __launch_bounds__(128, 1) void k1_conv(
    const float* __restrict__ x,  const float* __restrict__ w1,
    const float* __restrict__ b1, const float* __restrict__ w2,
    const float* __restrict__ b2)
{
    __shared__ __align__(16) float w1s[D1 * 3];
    __shared__ float b1s[D1];
    __shared__ __align__(16) float w2s[3 * D2 * D1];
    __shared__ float b2s[D2];

    const int s = blockIdx.y;
    const int tid = threadIdx.x;

    for (int i = tid; i < D1 * 3; i += 128) w1s[i] = w1[s * D1 * 3 + i];
    for (int i = tid; i < D1; i += 128)     b1s[i] = b1[s * D1 + i];
    for (int i = tid; i < D2; i += 128)     b2s[i] = b2[s * D2 + i];
    for (int i = tid; i < 3 * D2 * D1; i += 128) {
        int d2 = i / (D1 * 3);
        int r  = i % (D1 * 3);
        int d1 = r / 3;
        int k  = r % 3;
        w2s[(k * D2 + d2) * D1 + d1] = w2[s * D2 * D1 * 3 + i];
    }
    __syncthreads();

    const int b = blockIdx.x * 128 + tid;

    float xp[L + 2];
    xp[0] = 0.0f; xp[L + 1] = 0.0f;
    #pragma unroll
    for (int l = 0; l < L; ++l) xp[l + 1] = x[(b * S + s) * L + l];

    float h1[L][D1];
    #pragma unroll
    for (int l = 0; l < L; ++l) {
        #pragma unroll
        for (int d1 = 0; d1 < D1; ++d1) {
            float v = b1s[d1]
                    + w1s[d1 * 3 + 0] * xp[l]
                    + w1s[d1 * 3 + 1] * xp[l + 1]
                    + w1s[d1 * 3 + 2] * xp[l + 2];
            h1[l][d1] = gelu_exact(v);
        }
    }

    __nv_bfloat16* outHi = &g_ahi[(size_t)s * KDIM * BATCH + b];
    __nv_bfloat16* outLo = &g_alo[(size_t)s * KDIM * BATCH + b];
    for (int d2 = 0; d2 < D2; ++d2) {
        float acc[L];
        #pragma unroll
        for (int l = 0; l < L; ++l) acc[l] = b2s[d2];
        #pragma unroll
        for (int k = 0; k < 3; ++k) {
            const float4* wp = (const float4*)&w2s[(k * D2 + d2) * D1];
            #pragma unroll
            for (int q = 0; q < D1 / 4; ++q) {
                float4 w = wp[q];
                #pragma unroll
                for (int l = 0; l < L; ++l) {
                    int c = l + k - 1;
                    if (c >= 0 && c < L) {
                        acc[l] += w.x * h1[c][q * 4 + 0] + w.y * h1[c][q * 4 + 1]
                                + w.z * h1[c][q * 4 + 2] + w.w * h1[c][q * 4 + 3];
                    }
                }
            }
        }
        #pragma unroll
        for (int l = 0; l < L; ++l) {
            float v = gelu_exact(acc[l]);
            __nv_bfloat16 hi = __float2bfloat16(v);
            __nv_bfloat16 lo = __float2bfloat16(v - __bfloat162float(hi));
            size_t off = (size_t)(d2 * L + l) * BATCH;
            outHi[off] = hi;     // coalesced over b
            outLo[off] = lo;
        }
    }
}

// ============================================================================
// K2: per (s,j) sum / sumsq over b (reconstruct v = hi + lo, err ~2^-16)
// ============================================================================
__global__ void k2_stats()
{
    const int j = blockIdx.x, s = blockIdx.y, tid = threadIdx.x;
    const __nv_bfloat16* ph = &g_ahi[(size_t)(s * KDIM + j) * BATCH];
    const __nv_bfloat16* pl = &g_alo[(size_t)(s * KDIM + j) * BATCH];
    float s1 = 0.0f, s2 = 0.0f;
    for (int i = tid; i < BATCH; i += 256) {
        float v = __bfloat162float(ph[i]) + __bfloat162float(pl[i]);
        s1 += v;
        s2 += v * v;
    }
    __shared__ float r1[256], r2[256];
    r1[tid] = s1; r2[tid] = s2;
    __syncthreads();
    for (int off = 128; off > 0; off >>= 1) {
        if (tid < off) { r1[tid] += r1[tid + off]; r2[tid] += r2[tid + off]; }
        __syncthreads();
    }
    if (tid == 0) {
        g_sum1[s * KDIM + j] = r1[0];
        g_sum2[s * KDIM + j] = r2[0];
    }
}

// ============================================================================
// K3all: fused BN-finalize + weight split + bias.
// ============================================================================
__global__ __launch_bounds__(KDIM) void k3_all(
    const float* __restrict__ gamma, const float* __restrict__ beta,
    const float* __restrict__ wl,    const float* __restrict__ bl)
{
    const int bid = blockIdx.x, s = blockIdx.y, j = threadIdx.x;  // 320 threads
    __shared__ float sc_s[D2], sh_s[D2];
    if (j < D2) {
        float S1 = 0.0f, S2 = 0.0f;
        #pragma unroll
        for (int l = 0; l < L; ++l) {
            S1 += g_sum1[s * KDIM + j * L + l];
            S2 += g_sum2[s * KDIM + j * L + l];
        }
        const float invn = 1.0f / (float)(BATCH * L);
        float mean = S1 * invn;
        float var  = S2 * invn - mean * mean;
        float inv  = rsqrtf(var + EPSBN);
        float sc   = gamma[s * D2 + j] * inv;
        sc_s[j] = sc;
        sh_s[j] = beta[s * D2 + j] - mean * sc;
    }
    __syncthreads();

    if (bid < NPAD) {
        const int o = bid;
        float v = 0.0f;
        if (o < OUT) v = wl[((size_t)s * OUT + o) * KDIM + j] * sc_s[j / L];
        __nv_bfloat16 hi = __float2bfloat16(v);
        __nv_bfloat16 lo = __float2bfloat16(v - __bfloat162float(hi));
        size_t base = ((size_t)(s * NPAD + o)) * KDIM + j;
        g_bhi[base] = hi;
        g_blo[base] = lo;
    } else {
        const int o = bid - NPAD;   // < OUT
        float v = wl[((size_t)s * OUT + o) * KDIM + j] * sh_s[j / L];
        __shared__ float red[KDIM];
        red[j] = v;
        __syncthreads();
        if (j < 64)  red[j] += red[j + 256];
        __syncthreads();
        if (j < 128) red[j] += red[j + 128];
        __syncthreads();
        if (j < 64)  red[j] += red[j + 64];
        __syncthreads();
        if (j < 32) {
            float xv = red[j] + red[j + 32];
            #pragma unroll
            for (int off = 16; off > 0; off >>= 1)
                xv += __shfl_down_sync(0xffffffffu, xv, off);
            if (j == 0) g_bias[s * OUT + o] = bl[s * OUT + o] + xv;
        }
    }
}

// ============================================================================
// K6: HMMA split-GEMM.  out = Ahi*Bhi + Ahi*Blo + Alo*Bhi (+bias)
//   4-stage cp.async pipeline; split term OUTERMOST so consecutive MMAs hit
//   distinct accumulators (no RAW chains on the HMMA pipe).
// ============================================================================
__global__ __launch_bounds__(256, 1) void k6_gemm(float* __restrict__ out)
{
    extern __shared__ __align__(16) char dyn[];
    const uint32_t sbase = smem_u32(dyn);

    const int tid  = threadIdx.x;
    const int wid  = tid >> 5;
    const int lane = tid & 31;
    const int nt = blockIdx.x * BN;   // 0,192,384 (fastest -> A L2 reuse)
    const int bt = blockIdx.y * BM;
    const int s  = blockIdx.z;

    const int wm = (wid & 3) * 32;    // warp m offset
    const int wn = (wid >> 2) * 96;   // warp n offset

    const __nv_bfloat16* Ah = g_ahi + (size_t)s * KDIM * BATCH + bt;   // + j*BATCH
    const __nv_bfloat16* Al = g_alo + (size_t)s * KDIM * BATCH + bt;
    const __nv_bfloat16* Bh = g_bhi + ((size_t)(s * NPAD + nt)) * KDIM;
    const __nv_bfloat16* Bl = g_blo + ((size_t)(s * NPAD + nt)) * KDIM;

    float c[2][12][4];
    #pragma unroll
    for (int i = 0; i < 2; ++i)
        #pragma unroll
        for (int j = 0; j < 12; ++j)
            #pragma unroll
            for (int k = 0; k < 4; ++k) c[i][j][k] = 0.0f;

    auto load_stage = [&](int chunk) {
        const uint32_t st = sbase + (uint32_t)(chunk & (NSTAGE - 1)) * STAGE_BYTES;
        const int coff = chunk * BK;
        #pragma unroll
        for (int u = tid; u < BK * 16; u += 256) {
            int row = u >> 4, g = u & 15;
            uint32_t so = swzA(row, g);
            cp16(st + so,           Ah + (size_t)(coff + row) * BATCH + g * 8);
            cp16(st + A_BYTES + so, Al + (size_t)(coff + row) * BATCH + g * 8);
        }
        #pragma unroll
        for (int u = tid; u < BN * 4; u += 256) {
            int row = u >> 2, g = u & 3;
            uint32_t so = swz_off(row, g);
            cp16(st + 2 * A_BYTES + so,
                 (const char*)(Bh + (size_t)row * KDIM + coff) + g * 16);
            cp16(st + 2 * A_BYTES + B_BYTES + so,
                 (const char*)(Bl + (size_t)row * KDIM + coff) + g * 16);
        }
        cp_commit();
    };

    load_stage(0);
    load_stage(1);
    load_stage(2);

    #pragma unroll 1
    for (int ch = 0; ch < NCHUNK; ++ch) {
        cp_wait<2>();          // stage ch landed (<=2 younger groups in flight)
        __syncthreads();       // all threads see it; prev stage fully consumed

        const uint32_t st = sbase + (uint32_t)(ch & (NSTAGE - 1)) * STAGE_BYTES;
        const uint32_t aH = st;
        const uint32_t aL = st + A_BYTES;
        const uint32_t bH = st + 2 * A_BYTES;
        const uint32_t bL = st + 2 * A_BYTES + B_BYTES;

        #pragma unroll
        for (int ks = 0; ks < 2; ++ks) {
            uint32_t ahf[2][4], alf[2][4];
            #pragma unroll
            for (int mf = 0; mf < 2; ++mf) {
                int jr = ks * 16 + ((lane >> 4) << 3) + (lane & 7);
                int g  = (wm + mf * 16) / 8 + ((lane >> 3) & 1);
                uint32_t so = swzA(jr, g);
                ldm_x4_t(ahf[mf][0], ahf[mf][1], ahf[mf][2], ahf[mf][3], aH + so);
                ldm_x4_t(alf[mf][0], alf[mf][1], alf[mf][2], alf[mf][3], aL + so);
            }
            uint32_t bhf[12][2], blf[12][2];
            #pragma unroll
            for (int p = 0; p < 6; ++p) {
                int row = wn + p * 16 + ((lane >> 4) << 3) + (lane & 7);
                int g   = ks * 2 + ((lane >> 3) & 1);
                uint32_t so = swz_off(row, g);
                ldm_x4(bhf[2 * p][0], bhf[2 * p][1], bhf[2 * p + 1][0], bhf[2 * p + 1][1],
                       bH + so);
                ldm_x4(blf[2 * p][0], blf[2 * p][1], blf[2 * p + 1][0], blf[2 * p + 1][1],
                       bL + so);
            }
            // split term OUTERMOST: 24 independent accumulators between any
            // two MMAs that share an accumulator -> no RAW stalls on HMMA
            #pragma unroll
            for (int mf = 0; mf < 2; ++mf)
                #pragma unroll
                for (int nf = 0; nf < 12; ++nf)
                    mma16816(c[mf][nf], ahf[mf], bhf[nf]);
            #pragma unroll
            for (int mf = 0; mf < 2; ++mf)
                #pragma unroll
                for (int nf = 0; nf < 12; ++nf)
                    mma16816(c[mf][nf], ahf[mf], blf[nf]);
            #pragma unroll
            for (int mf = 0; mf < 2; ++mf)
                #pragma unroll
                for (int nf = 0; nf < 12; ++nf)
                    mma16816(c[mf][nf], alf[mf], bhf[nf]);
        }

        if (ch + 3 < NCHUNK) load_stage(ch + 3);   // overwrites buffer read at ch-1
    }

    // ---- epilogue: add bias, SCALAR stores (OUT=541 odd -> rows not 8B-aligned)
    const int mrow = lane >> 2;
    const int ncol = (lane & 3) * 2;
    #pragma unroll
    for (int mf = 0; mf < 2; ++mf) {
        #pragma unroll
        for (int half = 0; half < 2; ++half) {
            int m = bt + wm + mf * 16 + mrow + half * 8;
            float* orow = out + ((size_t)m * S + s) * OUT;
            #pragma unroll
            for (int nf = 0; nf < 12; ++nf) {
                int o = nt + wn + nf * 8 + ncol;
                if (o < OUT)     orow[o]     = c[mf][nf][2 * half + 0] + g_bias[s * OUT + o];
                if (o + 1 < OUT) orow[o + 1] = c[mf][nf][2 * half + 1] + g_bias[s * OUT + o + 1];
            }
        }
    }
}

// ============================================================================
extern "C" void kernel_launch(void* const* d_in, const int* in_sizes, int n_in,
                              void* d_out, int out_size)
{
    const float* x     = (const float*)d_in[0];
    const float* w1    = (const float*)d_in[1];
    const float* b1    = (const float*)d_in[2];
    const float* w2    = (const float*)d_in[3];
    const float* b2    = (const float*)d_in[4];
    const float* gamma = (const float*)d_in[5];
    const float* beta  = (const float*)d_in[6];
    const float* wl    = (const float*)d_in[7];
    const float* bl    = (const float*)d_in[8];
    float* out = (float*)d_out;

    cudaFuncSetAttribute(k6_gemm, cudaFuncAttributeMaxDynamicSharedMemorySize, DSMEM);

    k1_conv <<<dim3(BATCH / 128, S), 128>>>(x, w1, b1, w2, b2);
    k2_stats<<<dim3(KDIM, S), 256>>>();
    k3_all  <<<dim3(NPAD + OUT, S), KDIM>>>(gamma, beta, wl, bl);
    k6_gemm <<<dim3(NPAD / BN, BATCH / BM, S), 256, DSMEM>>>(out);
}

// round 9
// speedup vs baseline: 2.1431x; 1.1490x over previous
#include <cuda_runtime.h>
#include <cuda_fp16.h>
#include <math.h>
#include <stdint.h>

#define BATCH 32768
#define S 3
#define L 5
#define D1 32
#define D2 64
#define OUT 541
#define KDIM 320      // D2*L
#define NPAD 576      // padded N (3 x 192)
#define EPSBN 1e-5f

// GEMM tiling
#define BM 128
#define BN 192
#define BK 32
#define NCHUNK (KDIM / BK)      // 10
#define NSTAGE 4
#define A_BYTES (BK * 256)      // 32 j-rows x 256B (128 b cols fp16) = 8192
#define B_BYTES (BN * 64)       // 12288
#define STAGE_BYTES (2 * A_BYTES + B_BYTES)      // 28672
#define DSMEM (NSTAGE * STAGE_BYTES)             // 114688

// ---- device scratch (static: no allocations allowed) ----
__device__ __align__(16) __half g_ahi[(size_t)S * KDIM * BATCH];   // [s][j][b]
__device__ __align__(16) __half g_alo[(size_t)S * KDIM * BATCH];
__device__ __align__(16) __half g_bh [(size_t)S * NPAD * KDIM];    // [s][o][j]
__device__ float g_sum1[S * KDIM];
__device__ float g_sum2[S * KDIM];
__device__ float g_bias[S * OUT];

__device__ __forceinline__ float gelu_exact(float v) {
    return 0.5f * v * (1.0f + erff(v * 0.70710678118654752f));
}

// ---------------- portable PTX helpers (sm_80-era instructions only) --------
__device__ __forceinline__ uint32_t smem_u32(const void* p) {
    uint32_t a;
    asm("{ .reg .u64 t; cvta.to.shared.u64 t, %1; cvt.u32.u64 %0, t; }" : "=r"(a) : "l"(p));
    return a;
}
__device__ __forceinline__ void cp16(uint32_t dst, const void* src) {
    asm volatile("cp.async.cg.shared.global [%0], [%1], 16;" :: "r"(dst), "l"(src));
}
__device__ __forceinline__ void cp_commit() {
    asm volatile("cp.async.commit_group;" ::: "memory");
}
template<int N> __device__ __forceinline__ void cp_wait() {
    asm volatile("cp.async.wait_group %0;" :: "n"(N) : "memory");
}
__device__ __forceinline__ void ldm_x4(uint32_t& r0, uint32_t& r1, uint32_t& r2, uint32_t& r3,
                                       uint32_t addr) {
    asm volatile("ldmatrix.sync.aligned.m8n8.x4.shared.b16 {%0,%1,%2,%3}, [%4];"
                 : "=r"(r0), "=r"(r1), "=r"(r2), "=r"(r3) : "r"(addr));
}
__device__ __forceinline__ void ldm_x4_t(uint32_t& r0, uint32_t& r1, uint32_t& r2, uint32_t& r3,
                                         uint32_t addr) {
    asm volatile("ldmatrix.sync.aligned.m8n8.x4.trans.shared.b16 {%0,%1,%2,%3}, [%4];"
                 : "=r"(r0), "=r"(r1), "=r"(r2), "=r"(r3) : "r"(addr));
}
__device__ __forceinline__ void mma16816(float* c, const uint32_t* a, const uint32_t* b) {
    asm volatile(
        "mma.sync.aligned.m16n8k16.row.col.f32.f16.f16.f32 "
        "{%0,%1,%2,%3}, {%4,%5,%6,%7}, {%8,%9}, {%0,%1,%2,%3};"
        : "+f"(c[0]), "+f"(c[1]), "+f"(c[2]), "+f"(c[3])
        : "r"(a[0]), "r"(a[1]), "r"(a[2]), "r"(a[3]), "r"(b[0]), "r"(b[1]));
}
// B tile swizzle: 64B rows, 4 granules of 16B
__device__ __forceinline__ uint32_t swz_off(int row, int g) {
    return (uint32_t)(row * 64 + ((g ^ ((row >> 1) & 3)) << 4));
}
// A tile swizzle: 256B rows (128 fp16 b-cols), 16 granules of 16B
__device__ __forceinline__ uint32_t swzA(int row, int g) {
    return (uint32_t)(row * 256 + ((g ^ (row & 15)) << 4));
}

// ============================================================================
// K1: per (b,s) conv1 -> gelu -> conv2 -> gelu, write SPLIT fp16 hi/lo
//     directly to [s][j][b]  (A operand of the GEMM; BN folds into B side)
// ============================================================================
__global__ __launch_bounds__(128, 1) void k1_conv(
    const float* __restrict__ x,  const float* __restrict__ w1,
    const float* __restrict__ b1, const float* __restrict__ w2,
    const float* __restrict__ b2)
{
    __shared__ __align__(16) float w1s[D1 * 3];
    __shared__ float b1s[D1];
    __shared__ __align__(16) float w2s[3 * D2 * D1];
    __shared__ float b2s[D2];

    const int s = blockIdx.y;
    const int tid = threadIdx.x;

    for (int i = tid; i < D1 * 3; i += 128) w1s[i] = w1[s * D1 * 3 + i];
    for (int i = tid; i < D1; i += 128)     b1s[i] = b1[s * D1 + i];
    for (int i = tid; i < D2; i += 128)     b2s[i] = b2[s * D2 + i];
    for (int i = tid; i < 3 * D2 * D1; i += 128) {
        int d2 = i / (D1 * 3);
        int r  = i % (D1 * 3);
        int d1 = r / 3;
        int k  = r % 3;
        w2s[(k * D2 + d2) * D1 + d1] = w2[s * D2 * D1 * 3 + i];
    }
    __syncthreads();

    const int b = blockIdx.x * 128 + tid;

    float xp[L + 2];
    xp[0] = 0.0f; xp[L + 1] = 0.0f;
    #pragma unroll
    for (int l = 0; l < L; ++l) xp[l + 1] = x[(b * S + s) * L + l];

    float h1[L][D1];
    #pragma unroll
    for (int l = 0; l < L; ++l) {
        #pragma unroll
        for (int d1 = 0; d1 < D1; ++d1) {
            float v = b1s[d1]
                    + w1s[d1 * 3 + 0] * xp[l]
                    + w1s[d1 * 3 + 1] * xp[l + 1]
                    + w1s[d1 * 3 + 2] * xp[l + 2];
            h1[l][d1] = gelu_exact(v);
        }
    }

    __half* outHi = &g_ahi[(size_t)s * KDIM * BATCH + b];
    __half* outLo = &g_alo[(size_t)s * KDIM * BATCH + b];
    for (int d2 = 0; d2 < D2; ++d2) {
        float acc[L];
        #pragma unroll
        for (int l = 0; l < L; ++l) acc[l] = b2s[d2];
        #pragma unroll
        for (int k = 0; k < 3; ++k) {
            const float4* wp = (const float4*)&w2s[(k * D2 + d2) * D1];
            #pragma unroll
            for (int q = 0; q < D1 / 4; ++q) {
                float4 w = wp[q];
                #pragma unroll
                for (int l = 0; l < L; ++l) {
                    int c = l + k - 1;
                    if (c >= 0 && c < L) {
                        acc[l] += w.x * h1[c][q * 4 + 0] + w.y * h1[c][q * 4 + 1]
                                + w.z * h1[c][q * 4 + 2] + w.w * h1[c][q * 4 + 3];
                    }
                }
            }
        }
        #pragma unroll
        for (int l = 0; l < L; ++l) {
            float v = gelu_exact(acc[l]);
            __half hi = __float2half_rn(v);
            __half lo = __float2half_rn(v - __half2float(hi));
            size_t off = (size_t)(d2 * L + l) * BATCH;
            outHi[off] = hi;     // coalesced over b
            outLo[off] = lo;
        }
    }
}

// ============================================================================
// K2: per (s,j) sum / sumsq over b (reconstruct v = hi + lo, err ~2^-22)
// ============================================================================
__global__ void k2_stats()
{
    const int j = blockIdx.x, s = blockIdx.y, tid = threadIdx.x;
    const __half* ph = &g_ahi[(size_t)(s * KDIM + j) * BATCH];
    const __half* pl = &g_alo[(size_t)(s * KDIM + j) * BATCH];
    float s1 = 0.0f, s2 = 0.0f;
    for (int i = tid; i < BATCH; i += 256) {
        float v = __half2float(ph[i]) + __half2float(pl[i]);
        s1 += v;
        s2 += v * v;
    }
    __shared__ float r1[256], r2[256];
    r1[tid] = s1; r2[tid] = s2;
    __syncthreads();
    for (int off = 128; off > 0; off >>= 1) {
        if (tid < off) { r1[tid] += r1[tid + off]; r2[tid] += r2[tid + off]; }
        __syncthreads();
    }
    if (tid == 0) {
        g_sum1[s * KDIM + j] = r1[0];
        g_sum2[s * KDIM + j] = r2[0];
    }
}

// ============================================================================
// K3all: fused BN-finalize + weight fp16 + bias.
// ============================================================================
__global__ __launch_bounds__(KDIM) void k3_all(
    const float* __restrict__ gamma, const float* __restrict__ beta,
    const float* __restrict__ wl,    const float* __restrict__ bl)
{
    const int bid = blockIdx.x, s = blockIdx.y, j = threadIdx.x;  // 320 threads
    __shared__ float sc_s[D2], sh_s[D2];
    if (j < D2) {
        float S1 = 0.0f, S2 = 0.0f;
        #pragma unroll
        for (int l = 0; l < L; ++l) {
            S1 += g_sum1[s * KDIM + j * L + l];
            S2 += g_sum2[s * KDIM + j * L + l];
        }
        const float invn = 1.0f / (float)(BATCH * L);
        float mean = S1 * invn;
        float var  = S2 * invn - mean * mean;
        float inv  = rsqrtf(var + EPSBN);
        float sc   = gamma[s * D2 + j] * inv;
        sc_s[j] = sc;
        sh_s[j] = beta[s * D2 + j] - mean * sc;
    }
    __syncthreads();

    if (bid < NPAD) {
        const int o = bid;
        float v = 0.0f;
        if (o < OUT) v = wl[((size_t)s * OUT + o) * KDIM + j] * sc_s[j / L];
        g_bh[((size_t)(s * NPAD + o)) * KDIM + j] = __float2half_rn(v);
    } else {
        const int o = bid - NPAD;   // < OUT
        float v = wl[((size_t)s * OUT + o) * KDIM + j] * sh_s[j / L];
        __shared__ float red[KDIM];
        red[j] = v;
        __syncthreads();
        if (j < 64)  red[j] += red[j + 256];
        __syncthreads();
        if (j < 128) red[j] += red[j + 128];
        __syncthreads();
        if (j < 64)  red[j] += red[j + 64];
        __syncthreads();
        if (j < 32) {
            float xv = red[j] + red[j + 32];
            #pragma unroll
            for (int off = 16; off > 0; off >>= 1)
                xv += __shfl_down_sync(0xffffffffu, xv, off);
            if (j == 0) g_bias[s * OUT + o] = bl[s * OUT + o] + xv;
        }
    }
}

// ============================================================================
// K6: HMMA 2-term fp16 split-GEMM.  out = Ahi*B + Alo*B (+bias)
//   4-stage cp.async pipeline.
// ============================================================================
__global__ __launch_bounds__(256, 1) void k6_gemm(float* __restrict__ out)
{
    extern __shared__ __align__(16) char dyn[];
    const uint32_t sbase = smem_u32(dyn);

    const int tid  = threadIdx.x;
    const int wid  = tid >> 5;
    const int lane = tid & 31;
    const int nt = blockIdx.x * BN;   // 0,192,384 (fastest -> A L2 reuse)
    const int bt = blockIdx.y * BM;
    const int s  = blockIdx.z;

    const int wm = (wid & 3) * 32;    // warp m offset
    const int wn = (wid >> 2) * 96;   // warp n offset

    const __half* Ah = g_ahi + (size_t)s * KDIM * BATCH + bt;   // + j*BATCH
    const __half* Al = g_alo + (size_t)s * KDIM * BATCH + bt;
    const __half* Bh = g_bh  + ((size_t)(s * NPAD + nt)) * KDIM;

    float c[2][12][4];
    #pragma unroll
    for (int i = 0; i < 2; ++i)
        #pragma unroll
        for (int j = 0; j < 12; ++j)
            #pragma unroll
            for (int k = 0; k < 4; ++k) c[i][j][k] = 0.0f;

    auto load_stage = [&](int chunk) {
        const uint32_t st = sbase + (uint32_t)(chunk & (NSTAGE - 1)) * STAGE_BYTES;
        const int coff = chunk * BK;
        #pragma unroll
        for (int u = tid; u < BK * 16; u += 256) {
            int row = u >> 4, g = u & 15;
            uint32_t so = swzA(row, g);
            cp16(st + so,           Ah + (size_t)(coff + row) * BATCH + g * 8);
            cp16(st + A_BYTES + so, Al + (size_t)(coff + row) * BATCH + g * 8);
        }
        #pragma unroll
        for (int u = tid; u < BN * 4; u += 256) {
            int row = u >> 2, g = u & 3;
            uint32_t so = swz_off(row, g);
            cp16(st + 2 * A_BYTES + so,
                 (const char*)(Bh + (size_t)row * KDIM + coff) + g * 16);
        }
        cp_commit();
    };

    load_stage(0);
    load_stage(1);
    load_stage(2);

    #pragma unroll 1
    for (int ch = 0; ch < NCHUNK; ++ch) {
        cp_wait<2>();          // stage ch landed (<=2 younger groups in flight)
        __syncthreads();       // all threads see it; prev stage fully consumed

        const uint32_t st = sbase + (uint32_t)(ch & (NSTAGE - 1)) * STAGE_BYTES;
        const uint32_t aH = st;
        const uint32_t aL = st + A_BYTES;
        const uint32_t bH = st + 2 * A_BYTES;

        #pragma unroll
        for (int ks = 0; ks < 2; ++ks) {
            uint32_t ahf[2][4], alf[2][4];
            #pragma unroll
            for (int mf = 0; mf < 2; ++mf) {
                int jr = ks * 16 + ((lane >> 4) << 3) + (lane & 7);
                int g  = (wm + mf * 16) / 8 + ((lane >> 3) & 1);
                uint32_t so = swzA(jr, g);
                ldm_x4_t(ahf[mf][0], ahf[mf][1], ahf[mf][2], ahf[mf][3], aH + so);
                ldm_x4_t(alf[mf][0], alf[mf][1], alf[mf][2], alf[mf][3], aL + so);
            }
            uint32_t bhf[12][2];
            #pragma unroll
            for (int p = 0; p < 6; ++p) {
                int row = wn + p * 16 + ((lane >> 4) << 3) + (lane & 7);
                int g   = ks * 2 + ((lane >> 3) & 1);
                uint32_t so = swz_off(row, g);
                ldm_x4(bhf[2 * p][0], bhf[2 * p][1], bhf[2 * p + 1][0], bhf[2 * p + 1][1],
                       bH + so);
            }
            #pragma unroll
            for (int mf = 0; mf < 2; ++mf)
                #pragma unroll
                for (int nf = 0; nf < 12; ++nf)
                    mma16816(c[mf][nf], ahf[mf], bhf[nf]);
            #pragma unroll
            for (int mf = 0; mf < 2; ++mf)
                #pragma unroll
                for (int nf = 0; nf < 12; ++nf)
                    mma16816(c[mf][nf], alf[mf], bhf[nf]);
        }

        if (ch + 3 < NCHUNK) load_stage(ch + 3);   // overwrites buffer read at ch-1
    }

    // ---- epilogue: add bias, SCALAR stores (OUT=541 odd -> rows not 8B-aligned)
    const int mrow = lane >> 2;
    const int ncol = (lane & 3) * 2;
    #pragma unroll
    for (int mf = 0; mf < 2; ++mf) {
        #pragma unroll
        for (int half = 0; half < 2; ++half) {
            int m = bt + wm + mf * 16 + mrow + half * 8;
            float* orow = out + ((size_t)m * S + s) * OUT;
            #pragma unroll
            for (int nf = 0; nf < 12; ++nf) {
                int o = nt + wn + nf * 8 + ncol;
                if (o < OUT)     orow[o]     = c[mf][nf][2 * half + 0] + g_bias[s * OUT + o];
                if (o + 1 < OUT) orow[o + 1] = c[mf][nf][2 * half + 1] + g_bias[s * OUT + o + 1];
            }
        }
    }
}

// ============================================================================
extern "C" void kernel_launch(void* const* d_in, const int* in_sizes, int n_in,
                              void* d_out, int out_size)
{
    const float* x     = (const float*)d_in[0];
    const float* w1    = (const float*)d_in[1];
    const float* b1    = (const float*)d_in[2];
    const float* w2    = (const float*)d_in[3];
    const float* b2    = (const float*)d_in[4];
    const float* gamma = (const float*)d_in[5];
    const float* beta  = (const float*)d_in[6];
    const float* wl    = (const float*)d_in[7];
    const float* bl    = (const float*)d_in[8];
    float* out = (float*)d_out;

    cudaFuncSetAttribute(k6_gemm, cudaFuncAttributeMaxDynamicSharedMemorySize, DSMEM);

    k1_conv <<<dim3(BATCH / 128, S), 128>>>(x, w1, b1, w2, b2);
    k2_stats<<<dim3(KDIM, S), 256>>>();
    k3_all  <<<dim3(NPAD + OUT, S), KDIM>>>(gamma, beta, wl, bl);
    k6_gemm <<<dim3(NPAD / BN, BATCH / BM, S), 256, DSMEM>>>(out);
}

// round 11
// speedup vs baseline: 2.2484x; 1.0491x over previous
#include <cuda_runtime.h>
#include <cuda_fp16.h>
#include <math.h>
#include <stdint.h>

#define BATCH 32768
#define S 3
#define L 5
#define D1 32
#define D2 64
#define OUT 541
#define KDIM 320      // D2*L
#define NPAD 576      // padded N (3 x 192)
#define EPSBN 1e-5f

// GEMM tiling
#define BM 128
#define BN 192
#define BK 32
#define NCHUNK (KDIM / BK)      // 10
#define NSTAGE 4
#define A_BYTES (BK * 256)      // 32 j-rows x 256B (128 b cols fp16) = 8192
#define B_BYTES (BN * 64)       // 12288
#define STAGE_BYTES (2 * A_BYTES + B_BYTES)      // 28672
#define DSMEM (NSTAGE * STAGE_BYTES)             // 114688

// ---- device scratch (static: no allocations allowed) ----
__device__ __align__(16) __half g_ahi[(size_t)S * KDIM * BATCH];   // [s][j][b]
__device__ __align__(16) __half g_alo[(size_t)S * KDIM * BATCH];
__device__ __align__(16) __half g_bh [(size_t)S * NPAD * KDIM];    // [s][o][j]
__device__ float g_sum1[S * KDIM];
__device__ float g_sum2[S * KDIM];
__device__ float g_bias[S * OUT];

__device__ __forceinline__ float gelu_exact(float v) {
    return 0.5f * v * (1.0f + erff(v * 0.70710678118654752f));
}

// ---------------- packed f32x2 helpers (sm_100+ PTX, plain target OK) -------
__device__ __forceinline__ uint64_t pk2(float lo, float hi) {
    uint64_t p;
    asm("mov.b64 %0, {%1, %2};" : "=l"(p) : "f"(lo), "f"(hi));
    return p;
}
__device__ __forceinline__ void upk2(float& lo, float& hi, uint64_t p) {
    asm("mov.b64 {%0, %1}, %2;" : "=f"(lo), "=f"(hi) : "l"(p));
}
__device__ __forceinline__ uint64_t fma2(uint64_t a, uint64_t b, uint64_t c) {
    uint64_t d;
    asm("fma.rn.f32x2 %0, %1, %2, %3;" : "=l"(d) : "l"(a), "l"(b), "l"(c));
    return d;
}

// ---------------- portable PTX helpers (sm_80-era instructions only) --------
__device__ __forceinline__ uint32_t smem_u32(const void* p) {
    uint32_t a;
    asm("{ .reg .u64 t; cvta.to.shared.u64 t, %1; cvt.u32.u64 %0, t; }" : "=r"(a) : "l"(p));
    return a;
}
__device__ __forceinline__ void cp16(uint32_t dst, const void* src) {
    asm volatile("cp.async.cg.shared.global [%0], [%1], 16;" :: "r"(dst), "l"(src));
}
__device__ __forceinline__ void cp_commit() {
    asm volatile("cp.async.commit_group;" ::: "memory");
}
template<int N> __device__ __forceinline__ void cp_wait() {
    asm volatile("cp.async.wait_group %0;" :: "n"(N) : "memory");
}
__device__ __forceinline__ void ldm_x4(uint32_t& r0, uint32_t& r1, uint32_t& r2, uint32_t& r3,
                                       uint32_t addr) {
    asm volatile("ldmatrix.sync.aligned.m8n8.x4.shared.b16 {%0,%1,%2,%3}, [%4];"
                 : "=r"(r0), "=r"(r1), "=r"(r2), "=r"(r3) : "r"(addr));
}
__device__ __forceinline__ void ldm_x4_t(uint32_t& r0, uint32_t& r1, uint32_t& r2, uint32_t& r3,
                                         uint32_t addr) {
    asm volatile("ldmatrix.sync.aligned.m8n8.x4.trans.shared.b16 {%0,%1,%2,%3}, [%4];"
                 : "=r"(r0), "=r"(r1), "=r"(r2), "=r"(r3) : "r"(addr));
}
__device__ __forceinline__ void mma16816(float* c, const uint32_t* a, const uint32_t* b) {
    asm volatile(
        "mma.sync.aligned.m16n8k16.row.col.f32.f16.f16.f32 "
        "{%0,%1,%2,%3}, {%4,%5,%6,%7}, {%8,%9}, {%0,%1,%2,%3};"
        : "+f"(c[0]), "+f"(c[1]), "+f"(c[2]), "+f"(c[3])
        : "r"(a[0]), "r"(a[1]), "r"(a[2]), "r"(a[3]), "r"(b[0]), "r"(b[1]));
}
// B tile swizzle: 64B rows, 4 granules of 16B
__device__ __forceinline__ uint32_t swz_off(int row, int g) {
    return (uint32_t)(row * 64 + ((g ^ ((row >> 1) & 3)) << 4));
}
// A tile swizzle: 256B rows (128 fp16 b-cols), 16 granules of 16B
__device__ __forceinline__ uint32_t swzA(int row, int g) {
    return (uint32_t)(row * 256 + ((g ^ (row & 15)) << 4));
}

// ============================================================================
// K1: conv1 -> gelu -> conv2(f32x2 packed) -> gelu, SPLIT fp16 hi/lo [s][j][b]
// ============================================================================
__global__ __launch_bounds__(128, 1) void k1_conv(
    const float* __restrict__ x,  const float* __restrict__ w1,
    const float* __restrict__ b1, const float* __restrict__ w2,
    const float* __restrict__ b2)
{
    __shared__ __align__(16) float w1s[D1 * 3];
    __shared__ float b1s[D1];
    __shared__ __align__(16) float w2s[3 * D2 * D1];   // [k][d2][d1]
    __shared__ float b2s[D2];

    const int s = blockIdx.y;
    const int tid = threadIdx.x;

    for (int i = tid; i < D1 * 3; i += 128) w1s[i] = w1[s * D1 * 3 + i];
    for (int i = tid; i < D1; i += 128)     b1s[i] = b1[s * D1 + i];
    for (int i = tid; i < D2; i += 128)     b2s[i] = b2[s * D2 + i];
    for (int i = tid; i < 3 * D2 * D1; i += 128) {
        int d2 = i / (D1 * 3);
        int r  = i % (D1 * 3);
        int d1 = r / 3;
        int k  = r % 3;
        w2s[(k * D2 + d2) * D1 + d1] = w2[s * D2 * D1 * 3 + i];
    }
    __syncthreads();

    const int b = blockIdx.x * 128 + tid;

    float xp[L + 2];
    xp[0] = 0.0f; xp[L + 1] = 0.0f;
    #pragma unroll
    for (int l = 0; l < L; ++l) xp[l + 1] = x[(b * S + s) * L + l];

    // h1, packed along d1 pairs: hp[l][q] = (h1[l][2q], h1[l][2q+1])
    uint64_t hp[L][D1 / 2];
    #pragma unroll
    for (int l = 0; l < L; ++l) {
        #pragma unroll
        for (int q = 0; q < D1 / 2; ++q) {
            int d1a = 2 * q, d1b = 2 * q + 1;
            float va = b1s[d1a]
                     + w1s[d1a * 3 + 0] * xp[l]
                     + w1s[d1a * 3 + 1] * xp[l + 1]
                     + w1s[d1a * 3 + 2] * xp[l + 2];
            float vb = b1s[d1b]
                     + w1s[d1b * 3 + 0] * xp[l]
                     + w1s[d1b * 3 + 1] * xp[l + 1]
                     + w1s[d1b * 3 + 2] * xp[l + 2];
            hp[l][q] = pk2(gelu_exact(va), gelu_exact(vb));
        }
    }

    __half* outHi = &g_ahi[(size_t)s * KDIM * BATCH + b];
    __half* outLo = &g_alo[(size_t)s * KDIM * BATCH + b];
    for (int d2 = 0; d2 < D2; ++d2) {
        // lane-split accumulators: init (b2, 0); final = lo+hi
        uint64_t accp[L];
        uint64_t init = pk2(b2s[d2], 0.0f);
        #pragma unroll
        for (int l = 0; l < L; ++l) accp[l] = init;

        #pragma unroll
        for (int k = 0; k < 3; ++k) {
            const ulonglong2* wp = (const ulonglong2*)&w2s[(k * D2 + d2) * D1];
            #pragma unroll
            for (int qq = 0; qq < D1 / 4; ++qq) {   // 8 x LDS.128 = 2 w-pairs
                ulonglong2 wv = wp[qq];
                #pragma unroll
                for (int l = 0; l < L; ++l) {
                    int c = l + k - 1;
                    if (c >= 0 && c < L) {
                        accp[l] = fma2(wv.x, hp[c][2 * qq + 0], accp[l]);
                        accp[l] = fma2(wv.y, hp[c][2 * qq + 1], accp[l]);
                    }
                }
            }
        }
        #pragma unroll
        for (int l = 0; l < L; ++l) {
            float lo, hi;
            upk2(lo, hi, accp[l]);
            float v = gelu_exact(lo + hi);
            __half vh = __float2half_rn(v);
            __half vl = __float2half_rn(v - __half2float(vh));
            size_t off = (size_t)(d2 * L + l) * BATCH;
            outHi[off] = vh;     // coalesced over b
            outLo[off] = vl;
        }
    }
}

// ============================================================================
// K2: per (s,j) sum / sumsq over b (reconstruct v = hi + lo, err ~2^-22)
// ============================================================================
__global__ void k2_stats()
{
    const int j = blockIdx.x, s = blockIdx.y, tid = threadIdx.x;
    const __half2* ph = (const __half2*)&g_ahi[(size_t)(s * KDIM + j) * BATCH];
    const __half2* pl = (const __half2*)&g_alo[(size_t)(s * KDIM + j) * BATCH];
    float s1 = 0.0f, s2 = 0.0f;
    for (int i = tid; i < BATCH / 2; i += 256) {
        float2 a = __half22float2(ph[i]);
        float2 c = __half22float2(pl[i]);
        float v0 = a.x + c.x, v1 = a.y + c.y;
        s1 += v0 + v1;
        s2 += v0 * v0 + v1 * v1;
    }
    __shared__ float r1[256], r2[256];
    r1[tid] = s1; r2[tid] = s2;
    __syncthreads();
    for (int off = 128; off > 0; off >>= 1) {
        if (tid < off) { r1[tid] += r1[tid + off]; r2[tid] += r2[tid + off]; }
        __syncthreads();
    }
    if (tid == 0) {
        g_sum1[s * KDIM + j] = r1[0];
        g_sum2[s * KDIM + j] = r2[0];
    }
}

// ============================================================================
// K3all: fused BN-finalize + weight fp16 + bias.
// ============================================================================
__global__ __launch_bounds__(KDIM) void k3_all(
    const float* __restrict__ gamma, const float* __restrict__ beta,
    const float* __restrict__ wl,    const float* __restrict__ bl)
{
    const int bid = blockIdx.x, s = blockIdx.y, j = threadIdx.x;  // 320 threads
    __shared__ float sc_s[D2], sh_s[D2];
    if (j < D2) {
        float S1 = 0.0f, S2 = 0.0f;
        #pragma unroll
        for (int l = 0; l < L; ++l) {
            S1 += g_sum1[s * KDIM + j * L + l];
            S2 += g_sum2[s * KDIM + j * L + l];
        }
        const float invn = 1.0f / (float)(BATCH * L);
        float mean = S1 * invn;
        float var  = S2 * invn - mean * mean;
        float inv  = rsqrtf(var + EPSBN);
        float sc   = gamma[s * D2 + j] * inv;
        sc_s[j] = sc;
        sh_s[j] = beta[s * D2 + j] - mean * sc;
    }
    __syncthreads();

    if (bid < NPAD) {
        const int o = bid;
        float v = 0.0f;
        if (o < OUT) v = wl[((size_t)s * OUT + o) * KDIM + j] * sc_s[j / L];
        g_bh[((size_t)(s * NPAD + o)) * KDIM + j] = __float2half_rn(v);
    } else {
        const int o = bid - NPAD;   // < OUT
        float v = wl[((size_t)s * OUT + o) * KDIM + j] * sh_s[j / L];
        __shared__ float red[KDIM];
        red[j] = v;
        __syncthreads();
        if (j < 64)  red[j] += red[j + 256];
        __syncthreads();
        if (j < 128) red[j] += red[j + 128];
        __syncthreads();
        if (j < 64)  red[j] += red[j + 64];
        __syncthreads();
        if (j < 32) {
            float xv = red[j] + red[j + 32];
            #pragma unroll
            for (int off = 16; off > 0; off >>= 1)
                xv += __shfl_down_sync(0xffffffffu, xv, off);
            if (j == 0) g_bias[s * OUT + o] = bl[s * OUT + o] + xv;
        }
    }
}

// ============================================================================
// K6: HMMA 2-term fp16 split-GEMM (A exactly hi+lo; B single fp16).
//   4-stage cp.async pipeline.   [R9 config — A split is load-bearing: BN
//   cancellation amplifies uncentered-A quantization error ~60x.]
// ============================================================================
__global__ __launch_bounds__(256, 1) void k6_gemm(float* __restrict__ out)
{
    extern __shared__ __align__(16) char dyn[];
    const uint32_t sbase = smem_u32(dyn);

    const int tid  = threadIdx.x;
    const int wid  = tid >> 5;
    const int lane = tid & 31;
    const int nt = blockIdx.x * BN;   // 0,192,384 (fastest -> A L2 reuse)
    const int bt = blockIdx.y * BM;
    const int s  = blockIdx.z;

    const int wm = (wid & 3) * 32;    // warp m offset
    const int wn = (wid >> 2) * 96;   // warp n offset

    const __half* Ah = g_ahi + (size_t)s * KDIM * BATCH + bt;   // + j*BATCH
    const __half* Al = g_alo + (size_t)s * KDIM * BATCH + bt;
    const __half* Bp = g_bh  + ((size_t)(s * NPAD + nt)) * KDIM;

    float c[2][12][4];
    #pragma unroll
    for (int i = 0; i < 2; ++i)
        #pragma unroll
        for (int j = 0; j < 12; ++j)
            #pragma unroll
            for (int k = 0; k < 4; ++k) c[i][j][k] = 0.0f;

    auto load_stage = [&](int chunk) {
        const uint32_t st = sbase + (uint32_t)(chunk & (NSTAGE - 1)) * STAGE_BYTES;
        const int coff = chunk * BK;
        #pragma unroll
        for (int u = tid; u < BK * 16; u += 256) {
            int row = u >> 4, g = u & 15;
            uint32_t so = swzA(row, g);
            cp16(st + so,           Ah + (size_t)(coff + row) * BATCH + g * 8);
            cp16(st + A_BYTES + so, Al + (size_t)(coff + row) * BATCH + g * 8);
        }
        #pragma unroll
        for (int u = tid; u < BN * 4; u += 256) {
            int row = u >> 2, g = u & 3;
            cp16(st + 2 * A_BYTES + swz_off(row, g),
                 (const char*)(Bp + (size_t)row * KDIM + coff) + g * 16);
        }
        cp_commit();
    };

    load_stage(0);
    load_stage(1);
    load_stage(2);

    #pragma unroll 1
    for (int ch = 0; ch < NCHUNK; ++ch) {
        cp_wait<2>();          // stage ch landed (<=2 younger groups in flight)
        __syncthreads();       // all threads see it; prev stage fully consumed

        const uint32_t st = sbase + (uint32_t)(ch & (NSTAGE - 1)) * STAGE_BYTES;
        const uint32_t aH = st;
        const uint32_t aL = st + A_BYTES;
        const uint32_t bS = st + 2 * A_BYTES;

        #pragma unroll
        for (int ks = 0; ks < 2; ++ks) {
            uint32_t ahf[2][4], alf[2][4];
            #pragma unroll
            for (int mf = 0; mf < 2; ++mf) {
                int jr = ks * 16 + ((lane >> 4) << 3) + (lane & 7);
                int g  = (wm + mf * 16) / 8 + ((lane >> 3) & 1);
                uint32_t so = swzA(jr, g);
                ldm_x4_t(ahf[mf][0], ahf[mf][1], ahf[mf][2], ahf[mf][3], aH + so);
                ldm_x4_t(alf[mf][0], alf[mf][1], alf[mf][2], alf[mf][3], aL + so);
            }
            uint32_t bf[12][2];
            #pragma unroll
            for (int p = 0; p < 6; ++p) {
                int row = wn + p * 16 + ((lane >> 4) << 3) + (lane & 7);
                int g   = ks * 2 + ((lane >> 3) & 1);
                ldm_x4(bf[2 * p][0], bf[2 * p][1], bf[2 * p + 1][0], bf[2 * p + 1][1],
                       bS + swz_off(row, g));
            }
            #pragma unroll
            for (int mf = 0; mf < 2; ++mf)
                #pragma unroll
                for (int nf = 0; nf < 12; ++nf)
                    mma16816(c[mf][nf], ahf[mf], bf[nf]);
            #pragma unroll
            for (int mf = 0; mf < 2; ++mf)
                #pragma unroll
                for (int nf = 0; nf < 12; ++nf)
                    mma16816(c[mf][nf], alf[mf], bf[nf]);
        }

        if (ch + 3 < NCHUNK) load_stage(ch + 3);   // overwrites buffer read at ch-1
    }

    // ---- epilogue: add bias, SCALAR stores (OUT=541 odd -> rows not 8B-aligned)
    const int mrow = lane >> 2;
    const int ncol = (lane & 3) * 2;
    #pragma unroll
    for (int mf = 0; mf < 2; ++mf) {
        #pragma unroll
        for (int half = 0; half < 2; ++half) {
            int m = bt + wm + mf * 16 + mrow + half * 8;
            float* orow = out + ((size_t)m * S + s) * OUT;
            #pragma unroll
            for (int nf = 0; nf < 12; ++nf) {
                int o = nt + wn + nf * 8 + ncol;
                if (o < OUT)     orow[o]     = c[mf][nf][2 * half + 0] + g_bias[s * OUT + o];
                if (o + 1 < OUT) orow[o + 1] = c[mf][nf][2 * half + 1] + g_bias[s * OUT + o + 1];
            }
        }
    }
}

// ============================================================================
extern "C" void kernel_launch(void* const* d_in, const int* in_sizes, int n_in,
                              void* d_out, int out_size)
{
    const float* x     = (const float*)d_in[0];
    const float* w1    = (const float*)d_in[1];
    const float* b1    = (const float*)d_in[2];
    const float* w2    = (const float*)d_in[3];
    const float* b2    = (const float*)d_in[4];
    const float* gamma = (const float*)d_in[5];
    const float* beta  = (const float*)d_in[6];
    const float* wl    = (const float*)d_in[7];
    const float* bl    = (const float*)d_in[8];
    float* out = (float*)d_out;

    cudaFuncSetAttribute(k6_gemm, cudaFuncAttributeMaxDynamicSharedMemorySize, DSMEM);

    k1_conv <<<dim3(BATCH / 128, S), 128>>>(x, w1, b1, w2, b2);
    k2_stats<<<dim3(KDIM, S), 256>>>();
    k3_all  <<<dim3(NPAD + OUT, S), KDIM>>>(gamma, beta, wl, bl);
    k6_gemm <<<dim3(NPAD / BN, BATCH / BM, S), 256, DSMEM>>>(out);
}

// round 15
// speedup vs baseline: 2.6275x; 1.1686x over previous
#include <cuda_runtime.h>
#include <cuda_fp16.h>
#include <math.h>
#include <stdint.h>

#define BATCH 32768
#define S 3
#define L 5
#define D1 32
#define D2 64
#define OUT 541
#define KDIM 320      // D2*L
#define NPAD 576      // padded N (6 x 96)
#define EPSBN 1e-5f

// GEMM tiling
#define BM 128
#define BN 96
#define BK 32
#define NCHUNK (KDIM / BK)      // 10
#define NSTAGE 4
#define A_BYTES (BK * 256)      // 32 j-rows x 256B (128 b cols fp16) = 8192
#define B_BYTES (BN * 64)       // 6144
#define STAGE_BYTES (2 * A_BYTES + B_BYTES)      // 22528
#define DSMEM (NSTAGE * STAGE_BYTES)             // 90112  (x2 CTAs = 180224)

// ---- device scratch (static: no allocations allowed) ----
__device__ __align__(16) __half g_ahi[(size_t)S * KDIM * BATCH];   // [s][j][b]
__device__ __align__(16) __half g_alo[(size_t)S * KDIM * BATCH];
__device__ __align__(16) __half g_bh [(size_t)S * NPAD * KDIM];    // [s][o][j]
__device__ float g_sum1[S * KDIM];
__device__ float g_sum2[S * KDIM];
__device__ float g_bias[S * OUT];

__device__ __forceinline__ float gelu_exact(float v) {
    return 0.5f * v * (1.0f + erff(v * 0.70710678118654752f));
}

// ---------------- packed f32x2 helpers (sm_100+ PTX, plain target OK) -------
__device__ __forceinline__ uint64_t pk2(float lo, float hi) {
    uint64_t p;
    asm("mov.b64 %0, {%1, %2};" : "=l"(p) : "f"(lo), "f"(hi));
    return p;
}
__device__ __forceinline__ void upk2(float& lo, float& hi, uint64_t p) {
    asm("mov.b64 {%0, %1}, %2;" : "=f"(lo), "=f"(hi) : "l"(p));
}
__device__ __forceinline__ uint64_t fma2(uint64_t a, uint64_t b, uint64_t c) {
    uint64_t d;
    asm("fma.rn.f32x2 %0, %1, %2, %3;" : "=l"(d) : "l"(a), "l"(b), "l"(c));
    return d;
}

// ---------------- portable PTX helpers (sm_80-era instructions only) --------
__device__ __forceinline__ uint32_t smem_u32(const void* p) {
    uint32_t a;
    asm("{ .reg .u64 t; cvta.to.shared.u64 t, %1; cvt.u32.u64 %0, t; }" : "=r"(a) : "l"(p));
    return a;
}
__device__ __forceinline__ void cp16(uint32_t dst, const void* src) {
    asm volatile("cp.async.cg.shared.global [%0], [%1], 16;" :: "r"(dst), "l"(src));
}
__device__ __forceinline__ void cp_commit() {
    asm volatile("cp.async.commit_group;" ::: "memory");
}
template<int N> __device__ __forceinline__ void cp_wait() {
    asm volatile("cp.async.wait_group %0;" :: "n"(N) : "memory");
}
__device__ __forceinline__ void ldm_x4(uint32_t& r0, uint32_t& r1, uint32_t& r2, uint32_t& r3,
                                       uint32_t addr) {
    asm volatile("ldmatrix.sync.aligned.m8n8.x4.shared.b16 {%0,%1,%2,%3}, [%4];"
                 : "=r"(r0), "=r"(r1), "=r"(r2), "=r"(r3) : "r"(addr));
}
__device__ __forceinline__ void ldm_x4_t(uint32_t& r0, uint32_t& r1, uint32_t& r2, uint32_t& r3,
                                         uint32_t addr) {
    asm volatile("ldmatrix.sync.aligned.m8n8.x4.trans.shared.b16 {%0,%1,%2,%3}, [%4];"
                 : "=r"(r0), "=r"(r1), "=r"(r2), "=r"(r3) : "r"(addr));
}
__device__ __forceinline__ void mma16816(float* c, const uint32_t* a, const uint32_t* b) {
    asm volatile(
        "mma.sync.aligned.m16n8k16.row.col.f32.f16.f16.f32 "
        "{%0,%1,%2,%3}, {%4,%5,%6,%7}, {%8,%9}, {%0,%1,%2,%3};"
        : "+f"(c[0]), "+f"(c[1]), "+f"(c[2]), "+f"(c[3])
        : "r"(a[0]), "r"(a[1]), "r"(a[2]), "r"(a[3]), "r"(b[0]), "r"(b[1]));
}
// B tile swizzle: 64B rows, 4 granules of 16B
__device__ __forceinline__ uint32_t swz_off(int row, int g) {
    return (uint32_t)(row * 64 + ((g ^ ((row >> 1) & 3)) << 4));
}
// A tile swizzle: 256B rows (128 fp16 b-cols), 16 granules of 16B
__device__ __forceinline__ uint32_t swzA(int row, int g) {
    return (uint32_t)(row * 256 + ((g ^ (row & 15)) << 4));
}

// ============================================================================
// K1: conv1 -> gelu -> conv2(f32x2 packed) -> gelu, SPLIT fp16 hi/lo [s][j][b]
// ============================================================================
__global__ __launch_bounds__(128, 1) void k1_conv(
    const float* __restrict__ x,  const float* __restrict__ w1,
    const float* __restrict__ b1, const float* __restrict__ w2,
    const float* __restrict__ b2)
{
    __shared__ __align__(16) float w1s[D1 * 3];
    __shared__ float b1s[D1];
    __shared__ __align__(16) float w2s[3 * D2 * D1];   // [k][d2][d1]
    __shared__ float b2s[D2];

    const int s = blockIdx.y;
    const int tid = threadIdx.x;

    for (int i = tid; i < D1 * 3; i += 128) w1s[i] = w1[s * D1 * 3 + i];
    for (int i = tid; i < D1; i += 128)     b1s[i] = b1[s * D1 + i];
    for (int i = tid; i < D2; i += 128)     b2s[i] = b2[s * D2 + i];
    for (int i = tid; i < 3 * D2 * D1; i += 128) {
        int d2 = i / (D1 * 3);
        int r  = i % (D1 * 3);
        int d1 = r / 3;
        int k  = r % 3;
        w2s[(k * D2 + d2) * D1 + d1] = w2[s * D2 * D1 * 3 + i];
    }
    __syncthreads();

    const int b = blockIdx.x * 128 + tid;

    float xp[L + 2];
    xp[0] = 0.0f; xp[L + 1] = 0.0f;
    #pragma unroll
    for (int l = 0; l < L; ++l) xp[l + 1] = x[(b * S + s) * L + l];

    // h1, packed along d1 pairs: hp[l][q] = (h1[l][2q], h1[l][2q+1])
    uint64_t hp[L][D1 / 2];
    #pragma unroll
    for (int l = 0; l < L; ++l) {
        #pragma unroll
        for (int q = 0; q < D1 / 2; ++q) {
            int d1a = 2 * q, d1b = 2 * q + 1;
            float va = b1s[d1a]
                     + w1s[d1a * 3 + 0] * xp[l]
                     + w1s[d1a * 3 + 1] * xp[l + 1]
                     + w1s[d1a * 3 + 2] * xp[l + 2];
            float vb = b1s[d1b]
                     + w1s[d1b * 3 + 0] * xp[l]
                     + w1s[d1b * 3 + 1] * xp[l + 1]
                     + w1s[d1b * 3 + 2] * xp[l + 2];
            hp[l][q] = pk2(gelu_exact(va), gelu_exact(vb));
        }
    }

    __half* outHi = &g_ahi[(size_t)s * KDIM * BATCH + b];
    __half* outLo = &g_alo[(size_t)s * KDIM * BATCH + b];
    for (int d2 = 0; d2 < D2; ++d2) {
        // lane-split accumulators: init (b2, 0); final = lo+hi
        uint64_t accp[L];
        uint64_t init = pk2(b2s[d2], 0.0f);
        #pragma unroll
        for (int l = 0; l < L; ++l) accp[l] = init;

        #pragma unroll
        for (int k = 0; k < 3; ++k) {
            const ulonglong2* wp = (const ulonglong2*)&w2s[(k * D2 + d2) * D1];
            #pragma unroll
            for (int qq = 0; qq < D1 / 4; ++qq) {   // 8 x LDS.128 = 2 w-pairs
                ulonglong2 wv = wp[qq];
                #pragma unroll
                for (int l = 0; l < L; ++l) {
                    int c = l + k - 1;
                    if (c >= 0 && c < L) {
                        accp[l] = fma2(wv.x, hp[c][2 * qq + 0], accp[l]);
                        accp[l] = fma2(wv.y, hp[c][2 * qq + 1], accp[l]);
                    }
                }
            }
        }
        #pragma unroll
        for (int l = 0; l < L; ++l) {
            float lo, hi;
            upk2(lo, hi, accp[l]);
            float v = gelu_exact(lo + hi);
            __half vh = __float2half_rn(v);
            __half vl = __float2half_rn(v - __half2float(vh));
            size_t off = (size_t)(d2 * L + l) * BATCH;
            outHi[off] = vh;     // coalesced over b
            outLo[off] = vl;
        }
    }
}

// ============================================================================
// K2: per (s,j) sum / sumsq over b (reconstruct v = hi + lo, err ~2^-22)
// ============================================================================
__global__ void k2_stats()
{
    const int j = blockIdx.x, s = blockIdx.y, tid = threadIdx.x;
    const __half2* ph = (const __half2*)&g_ahi[(size_t)(s * KDIM + j) * BATCH];
    const __half2* pl = (const __half2*)&g_alo[(size_t)(s * KDIM + j) * BATCH];
    float s1 = 0.0f, s2 = 0.0f;
    for (int i = tid; i < BATCH / 2; i += 256) {
        float2 a = __half22float2(ph[i]);
        float2 c = __half22float2(pl[i]);
        float v0 = a.x + c.x, v1 = a.y + c.y;
        s1 += v0 + v1;
        s2 += v0 * v0 + v1 * v1;
    }
    __shared__ float r1[256], r2[256];
    r1[tid] = s1; r2[tid] = s2;
    __syncthreads();
    for (int off = 128; off > 0; off >>= 1) {
        if (tid < off) { r1[tid] += r1[tid + off]; r2[tid] += r2[tid + off]; }
        __syncthreads();
    }
    if (tid == 0) {
        g_sum1[s * KDIM + j] = r1[0];
        g_sum2[s * KDIM + j] = r2[0];
    }
}

// ============================================================================
// K3all: fused BN-finalize + weight fp16 + COMPENSATED bias.
//   bias_o = bl + sum_j ( wl*shift + (W - fp16(W)) * mean_j )
//   removes the mean-correlated (amplified) part of the fp16-B error exactly.
// ============================================================================
__global__ __launch_bounds__(KDIM) void k3_all(
    const float* __restrict__ gamma, const float* __restrict__ beta,
    const float* __restrict__ wl,    const float* __restrict__ bl)
{
    const int bid = blockIdx.x, s = blockIdx.y, j = threadIdx.x;  // 320 threads
    __shared__ float sc_s[D2], sh_s[D2];
    if (j < D2) {
        float S1 = 0.0f, S2 = 0.0f;
        #pragma unroll
        for (int l = 0; l < L; ++l) {
            S1 += g_sum1[s * KDIM + j * L + l];
            S2 += g_sum2[s * KDIM + j * L + l];
        }
        const float invn = 1.0f / (float)(BATCH * L);
        float mean = S1 * invn;
        float var  = S2 * invn - mean * mean;
        float inv  = rsqrtf(var + EPSBN);
        float sc   = gamma[s * D2 + j] * inv;
        sc_s[j] = sc;
        sh_s[j] = beta[s * D2 + j] - mean * sc;
    }
    __syncthreads();

    if (bid < NPAD) {
        const int o = bid;
        float v = 0.0f;
        if (o < OUT) v = wl[((size_t)s * OUT + o) * KDIM + j] * sc_s[j / L];
        g_bh[((size_t)(s * NPAD + o)) * KDIM + j] = __float2half_rn(v);
    } else {
        const int o = bid - NPAD;   // < OUT
        float W   = wl[((size_t)s * OUT + o) * KDIM + j] * sc_s[j / L];
        float Blo = W - __half2float(__float2half_rn(W));     // fp16 round error
        float meanj = g_sum1[s * KDIM + j] * (1.0f / (float)BATCH);  // per-j mean
        float v = wl[((size_t)s * OUT + o) * KDIM + j] * sh_s[j / L]
                + Blo * meanj;                                 // compensation
        __shared__ float red[KDIM];
        red[j] = v;
        __syncthreads();
        if (j < 64)  red[j] += red[j + 256];
        __syncthreads();
        if (j < 128) red[j] += red[j + 128];
        __syncthreads();
        if (j < 64)  red[j] += red[j + 64];
        __syncthreads();
        if (j < 32) {
            float xv = red[j] + red[j + 32];
            #pragma unroll
            for (int off = 16; off > 0; off >>= 1)
                xv += __shfl_down_sync(0xffffffffu, xv, off);
            if (j == 0) g_bias[s * OUT + o] = bl[s * OUT + o] + xv;
        }
    }
}

// ============================================================================
// K6: HMMA 2-term fp16 split-GEMM, CTA tile 128x96, 2 CTAs/SM.
//   4-stage cp.async pipeline with FIXED tail: a group is committed EVERY
//   iteration (empty group when no load), so cp_wait<2> always guarantees
//   stage ch has landed — including ch = NCHUNK-2 and NCHUNK-1.
// ============================================================================
__global__ __launch_bounds__(256, 2) void k6_gemm(float* __restrict__ out)
{
    extern __shared__ __align__(16) char dyn[];
    const uint32_t sbase = smem_u32(dyn);

    const int tid  = threadIdx.x;
    const int wid  = tid >> 5;
    const int lane = tid & 31;
    const int nt = blockIdx.x * BN;   // 0..480 step 96 (fastest -> A L2 reuse)
    const int bt = blockIdx.y * BM;
    const int s  = blockIdx.z;

    const int wm = (wid & 3) * 32;    // warp m offset
    const int wn = (wid >> 2) * 48;   // warp n offset

    const __half* Ah = g_ahi + (size_t)s * KDIM * BATCH + bt;   // + j*BATCH
    const __half* Al = g_alo + (size_t)s * KDIM * BATCH + bt;
    const __half* Bp = g_bh  + ((size_t)(s * NPAD + nt)) * KDIM;

    float c[2][6][4];
    #pragma unroll
    for (int i = 0; i < 2; ++i)
        #pragma unroll
        for (int j = 0; j < 6; ++j)
            #pragma unroll
            for (int k = 0; k < 4; ++k) c[i][j][k] = 0.0f;

    auto load_stage = [&](int chunk) {
        const uint32_t st = sbase + (uint32_t)(chunk & (NSTAGE - 1)) * STAGE_BYTES;
        const int coff = chunk * BK;
        #pragma unroll
        for (int u = tid; u < BK * 16; u += 256) {
            int row = u >> 4, g = u & 15;
            uint32_t so = swzA(row, g);
            cp16(st + so,           Ah + (size_t)(coff + row) * BATCH + g * 8);
            cp16(st + A_BYTES + so, Al + (size_t)(coff + row) * BATCH + g * 8);
        }
        #pragma unroll
        for (int u = tid; u < BN * 4; u += 256) {
            int row = u >> 2, g = u & 3;
            cp16(st + 2 * A_BYTES + swz_off(row, g),
                 (const char*)(Bp + (size_t)row * KDIM + coff) + g * 16);
        }
        cp_commit();
    };

    load_stage(0);
    load_stage(1);
    load_stage(2);

    #pragma unroll 1
    for (int ch = 0; ch < NCHUNK; ++ch) {
        cp_wait<2>();          // with per-iter commits: stages <= ch landed
        __syncthreads();       // all threads see it; prev stage fully consumed

        const uint32_t st = sbase + (uint32_t)(ch & (NSTAGE - 1)) * STAGE_BYTES;
        const uint32_t aH = st;
        const uint32_t aL = st + A_BYTES;
        const uint32_t bS = st + 2 * A_BYTES;

        #pragma unroll
        for (int ks = 0; ks < 2; ++ks) {
            uint32_t ahf[2][4], alf[2][4];
            #pragma unroll
            for (int mf = 0; mf < 2; ++mf) {
                int jr = ks * 16 + ((lane >> 4) << 3) + (lane & 7);
                int g  = (wm + mf * 16) / 8 + ((lane >> 3) & 1);
                uint32_t so = swzA(jr, g);
                ldm_x4_t(ahf[mf][0], ahf[mf][1], ahf[mf][2], ahf[mf][3], aH + so);
                ldm_x4_t(alf[mf][0], alf[mf][1], alf[mf][2], alf[mf][3], aL + so);
            }
            uint32_t bf[6][2];
            #pragma unroll
            for (int p = 0; p < 3; ++p) {
                int row = wn + p * 16 + ((lane >> 4) << 3) + (lane & 7);
                int g   = ks * 2 + ((lane >> 3) & 1);
                ldm_x4(bf[2 * p][0], bf[2 * p][1], bf[2 * p + 1][0], bf[2 * p + 1][1],
                       bS + swz_off(row, g));
            }
            #pragma unroll
            for (int mf = 0; mf < 2; ++mf)
                #pragma unroll
                for (int nf = 0; nf < 6; ++nf)
                    mma16816(c[mf][nf], ahf[mf], bf[nf]);
            #pragma unroll
            for (int mf = 0; mf < 2; ++mf)
                #pragma unroll
                for (int nf = 0; nf < 6; ++nf)
                    mma16816(c[mf][nf], alf[mf], bf[nf]);
        }

        if (ch + 3 < NCHUNK) load_stage(ch + 3);
        else                 cp_commit();          // empty group: keep cadence
    }

    // ---- epilogue: add bias, SCALAR stores (OUT=541 odd -> rows not 8B-aligned)
    const int mrow = lane >> 2;
    const int ncol = (lane & 3) * 2;
    #pragma unroll
    for (int mf = 0; mf < 2; ++mf) {
        #pragma unroll
        for (int half = 0; half < 2; ++half) {
            int m = bt + wm + mf * 16 + mrow + half * 8;
            float* orow = out + ((size_t)m * S + s) * OUT;
            #pragma unroll
            for (int nf = 0; nf < 6; ++nf) {
                int o = nt + wn + nf * 8 + ncol;
                if (o < OUT)     orow[o]     = c[mf][nf][2 * half + 0] + g_bias[s * OUT + o];
                if (o + 1 < OUT) orow[o + 1] = c[mf][nf][2 * half + 1] + g_bias[s * OUT + o + 1];
            }
        }
    }
}

// ============================================================================
extern "C" void kernel_launch(void* const* d_in, const int* in_sizes, int n_in,
                              void* d_out, int out_size)
{
    const float* x     = (const float*)d_in[0];
    const float* w1    = (const float*)d_in[1];
    const float* b1    = (const float*)d_in[2];
    const float* w2    = (const float*)d_in[3];
    const float* b2    = (const float*)d_in[4];
    const float* gamma = (const float*)d_in[5];
    const float* beta  = (const float*)d_in[6];
    const float* wl    = (const float*)d_in[7];
    const float* bl    = (const float*)d_in[8];
    float* out = (float*)d_out;

    cudaFuncSetAttribute(k6_gemm, cudaFuncAttributeMaxDynamicSharedMemorySize, DSMEM);

    k1_conv <<<dim3(BATCH / 128, S), 128>>>(x, w1, b1, w2, b2);
    k2_stats<<<dim3(KDIM, S), 256>>>();
    k3_all  <<<dim3(NPAD + OUT, S), KDIM>>>(gamma, beta, wl, bl);
    k6_gemm <<<dim3(NPAD / BN, BATCH / BM, S), 256, DSMEM>>>(out);
}

// round 16
// speedup vs baseline: 2.7608x; 1.0507x over previous
#include <cuda_runtime.h>
#include <cuda_fp16.h>
#include <math.h>
#include <stdint.h>

#define BATCH 32768
#define S 3
#define L 5
#define D1 32
#define D2 64
#define OUT 541
#define KDIM 320      // D2*L
#define NPAD 576      // padded N (6 x 96)
#define EPSBN 1e-5f

// GEMM tiling
#define BM 128
#define BN 96
#define BK 64
#define NCHUNK (KDIM / BK)      // 5
#define NSTAGE 2
#define A_BYTES (BK * 256)      // 64 j-rows x 256B (128 b cols fp16) = 16384
#define B_BYTES (BN * 128)     // 96 o-rows x 128B (64 k halves)     = 12288
#define STAGE_BYTES (2 * A_BYTES + B_BYTES)      // 45056
#define DSMEM (NSTAGE * STAGE_BYTES)             // 90112  (x2 CTAs = 180224)

// ---- device scratch (static: no allocations allowed) ----
__device__ __align__(16) __half g_ahi[(size_t)S * KDIM * BATCH];   // [s][j][b]
__device__ __align__(16) __half g_alo[(size_t)S * KDIM * BATCH];
__device__ __align__(16) __half g_bh [(size_t)S * NPAD * KDIM];    // [s][o][j]
__device__ float g_sum1[S * KDIM];
__device__ float g_sum2[S * KDIM];
__device__ float g_bias[S * OUT];

__device__ __forceinline__ float gelu_exact(float v) {
    return 0.5f * v * (1.0f + erff(v * 0.70710678118654752f));
}

// ---------------- packed f32x2 helpers ----------------
__device__ __forceinline__ uint64_t pk2(float lo, float hi) {
    uint64_t p;
    asm("mov.b64 %0, {%1, %2};" : "=l"(p) : "f"(lo), "f"(hi));
    return p;
}
__device__ __forceinline__ void upk2(float& lo, float& hi, uint64_t p) {
    asm("mov.b64 {%0, %1}, %2;" : "=f"(lo), "=f"(hi) : "l"(p));
}
__device__ __forceinline__ uint64_t fma2(uint64_t a, uint64_t b, uint64_t c) {
    uint64_t d;
    asm("fma.rn.f32x2 %0, %1, %2, %3;" : "=l"(d) : "l"(a), "l"(b), "l"(c));
    return d;
}

// ---------------- portable PTX helpers ----------------
__device__ __forceinline__ uint32_t smem_u32(const void* p) {
    uint32_t a;
    asm("{ .reg .u64 t; cvta.to.shared.u64 t, %1; cvt.u32.u64 %0, t; }" : "=r"(a) : "l"(p));
    return a;
}
__device__ __forceinline__ void cp16(uint32_t dst, const void* src) {
    asm volatile("cp.async.cg.shared.global [%0], [%1], 16;" :: "r"(dst), "l"(src));
}
__device__ __forceinline__ void cp_commit() {
    asm volatile("cp.async.commit_group;" ::: "memory");
}
template<int N> __device__ __forceinline__ void cp_wait() {
    asm volatile("cp.async.wait_group %0;" :: "n"(N) : "memory");
}
__device__ __forceinline__ void ldm_x4(uint32_t& r0, uint32_t& r1, uint32_t& r2, uint32_t& r3,
                                       uint32_t addr) {
    asm volatile("ldmatrix.sync.aligned.m8n8.x4.shared.b16 {%0,%1,%2,%3}, [%4];"
                 : "=r"(r0), "=r"(r1), "=r"(r2), "=r"(r3) : "r"(addr));
}
__device__ __forceinline__ void ldm_x4_t(uint32_t& r0, uint32_t& r1, uint32_t& r2, uint32_t& r3,
                                         uint32_t addr) {
    asm volatile("ldmatrix.sync.aligned.m8n8.x4.trans.shared.b16 {%0,%1,%2,%3}, [%4];"
                 : "=r"(r0), "=r"(r1), "=r"(r2), "=r"(r3) : "r"(addr));
}
__device__ __forceinline__ void mma16816(float* c, const uint32_t* a, const uint32_t* b) {
    asm volatile(
        "mma.sync.aligned.m16n8k16.row.col.f32.f16.f16.f32 "
        "{%0,%1,%2,%3}, {%4,%5,%6,%7}, {%8,%9}, {%0,%1,%2,%3};"
        : "+f"(c[0]), "+f"(c[1]), "+f"(c[2]), "+f"(c[3])
        : "r"(a[0]), "r"(a[1]), "r"(a[2]), "r"(a[3]), "r"(b[0]), "r"(b[1]));
}
// B tile swizzle: 128B rows, 8 granules of 16B
__device__ __forceinline__ uint32_t swzB(int row, int g) {
    return (uint32_t)(row * 128 + ((g ^ (row & 7)) << 4));
}
// A tile swizzle: 256B rows (128 fp16 b-cols), 16 granules of 16B
__device__ __forceinline__ uint32_t swzA(int row, int g) {
    return (uint32_t)(row * 256 + ((g ^ (row & 15)) << 4));
}

// ============================================================================
// K1: conv1 -> gelu -> conv2(f32x2 packed) -> gelu, SPLIT fp16 hi/lo [s][j][b]
// ============================================================================
__global__ __launch_bounds__(128, 1) void k1_conv(
    const float* __restrict__ x,  const float* __restrict__ w1,
    const float* __restrict__ b1, const float* __restrict__ w2,
    const float* __restrict__ b2)
{
    __shared__ __align__(16) float w1s[D1 * 3];
    __shared__ float b1s[D1];
    __shared__ __align__(16) float w2s[3 * D2 * D1];   // [k][d2][d1]
    __shared__ float b2s[D2];

    const int s = blockIdx.y;
    const int tid = threadIdx.x;

    for (int i = tid; i < D1 * 3; i += 128) w1s[i] = w1[s * D1 * 3 + i];
    for (int i = tid; i < D1; i += 128)     b1s[i] = b1[s * D1 + i];
    for (int i = tid; i < D2; i += 128)     b2s[i] = b2[s * D2 + i];
    for (int i = tid; i < 3 * D2 * D1; i += 128) {
        int d2 = i / (D1 * 3);
        int r  = i % (D1 * 3);
        int d1 = r / 3;
        int k  = r % 3;
        w2s[(k * D2 + d2) * D1 + d1] = w2[s * D2 * D1 * 3 + i];
    }
    __syncthreads();

    const int b = blockIdx.x * 128 + tid;

    float xp[L + 2];
    xp[0] = 0.0f; xp[L + 1] = 0.0f;
    #pragma unroll
    for (int l = 0; l < L; ++l) xp[l + 1] = x[(b * S + s) * L + l];

    uint64_t hp[L][D1 / 2];
    #pragma unroll
    for (int l = 0; l < L; ++l) {
        #pragma unroll
        for (int q = 0; q < D1 / 2; ++q) {
            int d1a = 2 * q, d1b = 2 * q + 1;
            float va = b1s[d1a]
                     + w1s[d1a * 3 + 0] * xp[l]
                     + w1s[d1a * 3 + 1] * xp[l + 1]
                     + w1s[d1a * 3 + 2] * xp[l + 2];
            float vb = b1s[d1b]
                     + w1s[d1b * 3 + 0] * xp[l]
                     + w1s[d1b * 3 + 1] * xp[l + 1]
                     + w1s[d1b * 3 + 2] * xp[l + 2];
            hp[l][q] = pk2(gelu_exact(va), gelu_exact(vb));
        }
    }

    __half* outHi = &g_ahi[(size_t)s * KDIM * BATCH + b];
    __half* outLo = &g_alo[(size_t)s * KDIM * BATCH + b];
    for (int d2 = 0; d2 < D2; ++d2) {
        uint64_t accp[L];
        uint64_t init = pk2(b2s[d2], 0.0f);
        #pragma unroll
        for (int l = 0; l < L; ++l) accp[l] = init;

        #pragma unroll
        for (int k = 0; k < 3; ++k) {
            const ulonglong2* wp = (const ulonglong2*)&w2s[(k * D2 + d2) * D1];
            #pragma unroll
            for (int qq = 0; qq < D1 / 4; ++qq) {
                ulonglong2 wv = wp[qq];
                #pragma unroll
                for (int l = 0; l < L; ++l) {
                    int c = l + k - 1;
                    if (c >= 0 && c < L) {
                        accp[l] = fma2(wv.x, hp[c][2 * qq + 0], accp[l]);
                        accp[l] = fma2(wv.y, hp[c][2 * qq + 1], accp[l]);
                    }
                }
            }
        }
        #pragma unroll
        for (int l = 0; l < L; ++l) {
            float lo, hi;
            upk2(lo, hi, accp[l]);
            float v = gelu_exact(lo + hi);
            __half vh = __float2half_rn(v);
            __half vl = __float2half_rn(v - __half2float(vh));
            size_t off = (size_t)(d2 * L + l) * BATCH;
            outHi[off] = vh;
            outLo[off] = vl;
        }
    }
}

// ============================================================================
// K2: per (s,j) sum / sumsq over b, uint4 (8-half) loads
// ============================================================================
__global__ void k2_stats()
{
    const int j = blockIdx.x, s = blockIdx.y, tid = threadIdx.x;
    const uint4* ph = (const uint4*)&g_ahi[(size_t)(s * KDIM + j) * BATCH];
    const uint4* pl = (const uint4*)&g_alo[(size_t)(s * KDIM + j) * BATCH];
    float s1 = 0.0f, s2 = 0.0f;
    for (int i = tid; i < BATCH / 8; i += 256) {
        uint4 a4 = ph[i];
        uint4 c4 = pl[i];
        const uint32_t* aw = (const uint32_t*)&a4;
        const uint32_t* cw = (const uint32_t*)&c4;
        #pragma unroll
        for (int w = 0; w < 4; ++w) {
            float2 a = __half22float2(*(const __half2*)&aw[w]);
            float2 c = __half22float2(*(const __half2*)&cw[w]);
            float v0 = a.x + c.x, v1 = a.y + c.y;
            s1 += v0 + v1;
            s2 += v0 * v0 + v1 * v1;
        }
    }
    __shared__ float r1[256], r2[256];
    r1[tid] = s1; r2[tid] = s2;
    __syncthreads();
    for (int off = 128; off > 0; off >>= 1) {
        if (tid < off) { r1[tid] += r1[tid + off]; r2[tid] += r2[tid + off]; }
        __syncthreads();
    }
    if (tid == 0) {
        g_sum1[s * KDIM + j] = r1[0];
        g_sum2[s * KDIM + j] = r2[0];
    }
}

// ============================================================================
// K3all: fused BN-finalize + weight fp16 + COMPENSATED bias.
// ============================================================================
__global__ __launch_bounds__(KDIM) void k3_all(
    const float* __restrict__ gamma, const float* __restrict__ beta,
    const float* __restrict__ wl,    const float* __restrict__ bl)
{
    const int bid = blockIdx.x, s = blockIdx.y, j = threadIdx.x;  // 320 threads
    __shared__ float sc_s[D2], sh_s[D2];
    if (j < D2) {
        float S1 = 0.0f, S2 = 0.0f;
        #pragma unroll
        for (int l = 0; l < L; ++l) {
            S1 += g_sum1[s * KDIM + j * L + l];
            S2 += g_sum2[s * KDIM + j * L + l];
        }
        const float invn = 1.0f / (float)(BATCH * L);
        float mean = S1 * invn;
        float var  = S2 * invn - mean * mean;
        float inv  = rsqrtf(var + EPSBN);
        float sc   = gamma[s * D2 + j] * inv;
        sc_s[j] = sc;
        sh_s[j] = beta[s * D2 + j] - mean * sc;
    }
    __syncthreads();

    if (bid < NPAD) {
        const int o = bid;
        float v = 0.0f;
        if (o < OUT) v = wl[((size_t)s * OUT + o) * KDIM + j] * sc_s[j / L];
        g_bh[((size_t)(s * NPAD + o)) * KDIM + j] = __float2half_rn(v);
    } else {
        const int o = bid - NPAD;   // < OUT
        float W   = wl[((size_t)s * OUT + o) * KDIM + j] * sc_s[j / L];
        float Blo = W - __half2float(__float2half_rn(W));
        float meanj = g_sum1[s * KDIM + j] * (1.0f / (float)BATCH);
        float v = wl[((size_t)s * OUT + o) * KDIM + j] * sh_s[j / L]
                + Blo * meanj;
        __shared__ float red[KDIM];
        red[j] = v;
        __syncthreads();
        if (j < 64)  red[j] += red[j + 256];
        __syncthreads();
        if (j < 128) red[j] += red[j + 128];
        __syncthreads();
        if (j < 64)  red[j] += red[j + 64];
        __syncthreads();
        if (j < 32) {
            float xv = red[j] + red[j + 32];
            #pragma unroll
            for (int off = 16; off > 0; off >>= 1)
                xv += __shfl_down_sync(0xffffffffu, xv, off);
            if (j == 0) g_bias[s * OUT + o] = bl[s * OUT + o] + xv;
        }
    }
}

// ============================================================================
// K6: HMMA 2-term fp16 split-GEMM, CTA 128x96, BK=64, 2 stages, 2 CTAs/SM.
//   5 K-chunks of 64 (4 mma-ksteps each) -> half the per-chunk bubbles.
//   Commit cadence maintained in the tail (empty groups) so cp_wait<1>
//   always guarantees the current stage has landed.
// ============================================================================
__global__ __launch_bounds__(256, 2) void k6_gemm(float* __restrict__ out)
{
    extern __shared__ __align__(16) char dyn[];
    const uint32_t sbase = smem_u32(dyn);

    const int tid  = threadIdx.x;
    const int wid  = tid >> 5;
    const int lane = tid & 31;
    const int nt = blockIdx.x * BN;   // fastest -> A L2 reuse
    const int bt = blockIdx.y * BM;
    const int s  = blockIdx.z;

    const int wm = (wid & 3) * 32;    // warp m offset
    const int wn = (wid >> 2) * 48;   // warp n offset

    const __half* Ah = g_ahi + (size_t)s * KDIM * BATCH + bt;   // + j*BATCH
    const __half* Al = g_alo + (size_t)s * KDIM * BATCH + bt;
    const __half* Bp = g_bh  + ((size_t)(s * NPAD + nt)) * KDIM;

    float c[2][6][4];
    #pragma unroll
    for (int i = 0; i < 2; ++i)
        #pragma unroll
        for (int j = 0; j < 6; ++j)
            #pragma unroll
            for (int k = 0; k < 4; ++k) c[i][j][k] = 0.0f;

    auto load_stage = [&](int chunk) {
        const uint32_t st = sbase + (uint32_t)(chunk & (NSTAGE - 1)) * STAGE_BYTES;
        const int coff = chunk * BK;
        // A hi/lo: 64 j-rows x 16 granules of 16B (8 b's each)
        #pragma unroll
        for (int u = tid; u < BK * 16; u += 256) {
            int row = u >> 4, g = u & 15;
            uint32_t so = swzA(row, g);
            cp16(st + so,           Ah + (size_t)(coff + row) * BATCH + g * 8);
            cp16(st + A_BYTES + so, Al + (size_t)(coff + row) * BATCH + g * 8);
        }
        // B: 96 o-rows x 8 granules of 16B (64 k-halves per row)
        #pragma unroll
        for (int u = tid; u < BN * 8; u += 256) {
            int row = u >> 3, g = u & 7;
            cp16(st + 2 * A_BYTES + swzB(row, g),
                 (const char*)(Bp + (size_t)row * KDIM + coff) + g * 16);
        }
        cp_commit();
    };

    load_stage(0);
    load_stage(1);

    #pragma unroll 1
    for (int ch = 0; ch < NCHUNK; ++ch) {
        cp_wait<1>();          // with per-iter commits: stage ch landed
        __syncthreads();

        const uint32_t st = sbase + (uint32_t)(ch & (NSTAGE - 1)) * STAGE_BYTES;
        const uint32_t aH = st;
        const uint32_t aL = st + A_BYTES;
        const uint32_t bS = st + 2 * A_BYTES;

        #pragma unroll
        for (int ks = 0; ks < 4; ++ks) {
            uint32_t ahf[2][4], alf[2][4];
            #pragma unroll
            for (int mf = 0; mf < 2; ++mf) {
                int jr = ks * 16 + ((lane >> 4) << 3) + (lane & 7);
                int g  = (wm + mf * 16) / 8 + ((lane >> 3) & 1);
                uint32_t so = swzA(jr, g);
                ldm_x4_t(ahf[mf][0], ahf[mf][1], ahf[mf][2], ahf[mf][3], aH + so);
                ldm_x4_t(alf[mf][0], alf[mf][1], alf[mf][2], alf[mf][3], aL + so);
            }
            uint32_t bf[6][2];
            #pragma unroll
            for (int p = 0; p < 3; ++p) {
                int row = wn + p * 16 + ((lane >> 4) << 3) + (lane & 7);
                int g   = ks * 2 + ((lane >> 3) & 1);
                ldm_x4(bf[2 * p][0], bf[2 * p][1], bf[2 * p + 1][0], bf[2 * p + 1][1],
                       bS + swzB(row, g));
            }
            #pragma unroll
            for (int mf = 0; mf < 2; ++mf)
                #pragma unroll
                for (int nf = 0; nf < 6; ++nf)
                    mma16816(c[mf][nf], ahf[mf], bf[nf]);
            #pragma unroll
            for (int mf = 0; mf < 2; ++mf)
                #pragma unroll
                for (int nf = 0; nf < 6; ++nf)
                    mma16816(c[mf][nf], alf[mf], bf[nf]);
        }

        __syncthreads();       // everyone done reading stage ch before overwrite
        if (ch + 2 < NCHUNK) load_stage(ch + 2);
        else                 cp_commit();          // keep group cadence in tail
    }

    // ---- epilogue: add bias, SCALAR stores (OUT=541 odd -> rows not 8B-aligned)
    const int mrow = lane >> 2;
    const int ncol = (lane & 3) * 2;
    #pragma unroll
    for (int mf = 0; mf < 2; ++mf) {
        #pragma unroll
        for (int half = 0; half < 2; ++half) {
            int m = bt + wm + mf * 16 + mrow + half * 8;
            float* orow = out + ((size_t)m * S + s) * OUT;
            #pragma unroll
            for (int nf = 0; nf < 6; ++nf) {
                int o = nt + wn + nf * 8 + ncol;
                if (o < OUT)     orow[o]     = c[mf][nf][2 * half + 0] + g_bias[s * OUT + o];
                if (o + 1 < OUT) orow[o + 1] = c[mf][nf][2 * half + 1] + g_bias[s * OUT + o + 1];
            }
        }
    }
}

// ============================================================================
extern "C" void kernel_launch(void* const* d_in, const int* in_sizes, int n_in,
                              void* d_out, int out_size)
{
    const float* x     = (const float*)d_in[0];
    const float* w1    = (const float*)d_in[1];
    const float* b1    = (const float*)d_in[2];
    const float* w2    = (const float*)d_in[3];
    const float* b2    = (const float*)d_in[4];
    const float* gamma = (const float*)d_in[5];
    const float* beta  = (const float*)d_in[6];
    const float* wl    = (const float*)d_in[7];
    const float* bl    = (const float*)d_in[8];
    float* out = (float*)d_out;

    cudaFuncSetAttribute(k6_gemm, cudaFuncAttributeMaxDynamicSharedMemorySize, DSMEM);

    k1_conv <<<dim3(BATCH / 128, S), 128>>>(x, w1, b1, w2, b2);
    k2_stats<<<dim3(KDIM, S), 256>>>();
    k3_all  <<<dim3(NPAD + OUT, S), KDIM>>>(gamma, beta, wl, bl);
    k6_gemm <<<dim3(NPAD / BN, BATCH / BM, S), 256, DSMEM>>>(out);
}

// round 17
// speedup vs baseline: 2.7833x; 1.0081x over previous
#include <cuda_runtime.h>
#include <cuda_fp16.h>
#include <math.h>
#include <stdint.h>

#define BATCH 32768
#define S 3
#define L 5
#define D1 32
#define D2 64
#define OUT 541
#define KDIM 320      // D2*L
#define NPAD 576      // padded N (6 x 96)
#define EPSBN 1e-5f

// GEMM tiling
#define BM 64
#define BN 96
#define BK 64
#define NCHUNK (KDIM / BK)      // 5
#define NSTAGE 2
#define A_BYTES (BK * 128)      // 64 j-rows x 128B (64 b cols fp16) = 8192
#define B_BYTES (BN * 128)      // 96 o-rows x 128B (64 k halves)   = 12288
#define STAGE_BYTES (2 * A_BYTES + B_BYTES)      // 28672
#define DSMEM (NSTAGE * STAGE_BYTES)             // 57344  (x3 CTAs = 172032)

// ---- device scratch (static: no allocations allowed) ----
__device__ __align__(16) __half g_ahi[(size_t)S * KDIM * BATCH];   // [s][j][b]
__device__ __align__(16) __half g_alo[(size_t)S * KDIM * BATCH];
__device__ __align__(16) __half g_bh [(size_t)S * NPAD * KDIM];    // [s][o][j]
__device__ float g_sum1[S * KDIM];
__device__ float g_sum2[S * KDIM];
__device__ float g_bias[S * OUT];

__device__ __forceinline__ float gelu_exact(float v) {
    return 0.5f * v * (1.0f + erff(v * 0.70710678118654752f));
}

// ---------------- packed f32x2 helpers ----------------
__device__ __forceinline__ uint64_t pk2(float lo, float hi) {
    uint64_t p;
    asm("mov.b64 %0, {%1, %2};" : "=l"(p) : "f"(lo), "f"(hi));
    return p;
}
__device__ __forceinline__ void upk2(float& lo, float& hi, uint64_t p) {
    asm("mov.b64 {%0, %1}, %2;" : "=f"(lo), "=f"(hi) : "l"(p));
}
__device__ __forceinline__ uint64_t fma2(uint64_t a, uint64_t b, uint64_t c) {
    uint64_t d;
    asm("fma.rn.f32x2 %0, %1, %2, %3;" : "=l"(d) : "l"(a), "l"(b), "l"(c));
    return d;
}

// ---------------- portable PTX helpers ----------------
__device__ __forceinline__ uint32_t smem_u32(const void* p) {
    uint32_t a;
    asm("{ .reg .u64 t; cvta.to.shared.u64 t, %1; cvt.u32.u64 %0, t; }" : "=r"(a) : "l"(p));
    return a;
}
__device__ __forceinline__ void cp16(uint32_t dst, const void* src) {
    asm volatile("cp.async.cg.shared.global [%0], [%1], 16;" :: "r"(dst), "l"(src));
}
__device__ __forceinline__ void cp_commit() {
    asm volatile("cp.async.commit_group;" ::: "memory");
}
template<int N> __device__ __forceinline__ void cp_wait() {
    asm volatile("cp.async.wait_group %0;" :: "n"(N) : "memory");
}
__device__ __forceinline__ void ldm_x4(uint32_t& r0, uint32_t& r1, uint32_t& r2, uint32_t& r3,
                                       uint32_t addr) {
    asm volatile("ldmatrix.sync.aligned.m8n8.x4.shared.b16 {%0,%1,%2,%3}, [%4];"
                 : "=r"(r0), "=r"(r1), "=r"(r2), "=r"(r3) : "r"(addr));
}
__device__ __forceinline__ void ldm_x4_t(uint32_t& r0, uint32_t& r1, uint32_t& r2, uint32_t& r3,
                                         uint32_t addr) {
    asm volatile("ldmatrix.sync.aligned.m8n8.x4.trans.shared.b16 {%0,%1,%2,%3}, [%4];"
                 : "=r"(r0), "=r"(r1), "=r"(r2), "=r"(r3) : "r"(addr));
}
__device__ __forceinline__ void mma16816(float* c, const uint32_t* a, const uint32_t* b) {
    asm volatile(
        "mma.sync.aligned.m16n8k16.row.col.f32.f16.f16.f32 "
        "{%0,%1,%2,%3}, {%4,%5,%6,%7}, {%8,%9}, {%0,%1,%2,%3};"
        : "+f"(c[0]), "+f"(c[1]), "+f"(c[2]), "+f"(c[3])
        : "r"(a[0]), "r"(a[1]), "r"(a[2]), "r"(a[3]), "r"(b[0]), "r"(b[1]));
}
// 128B-row swizzle: 8 granules of 16B, XOR by (row & 7)
__device__ __forceinline__ uint32_t swz128(int row, int g) {
    return (uint32_t)(row * 128 + ((g ^ (row & 7)) << 4));
}

// ============================================================================
// K1: conv1 -> gelu -> conv2(f32x2 packed) -> gelu, SPLIT fp16 hi/lo [s][j][b]
// ============================================================================
__global__ __launch_bounds__(128, 1) void k1_conv(
    const float* __restrict__ x,  const float* __restrict__ w1,
    const float* __restrict__ b1, const float* __restrict__ w2,
    const float* __restrict__ b2)
{
    __shared__ __align__(16) float w1s[D1 * 3];
    __shared__ float b1s[D1];
    __shared__ __align__(16) float w2s[3 * D2 * D1];   // [k][d2][d1]
    __shared__ float b2s[D2];

    const int s = blockIdx.y;
    const int tid = threadIdx.x;

    for (int i = tid; i < D1 * 3; i += 128) w1s[i] = w1[s * D1 * 3 + i];
    for (int i = tid; i < D1; i += 128)     b1s[i] = b1[s * D1 + i];
    for (int i = tid; i < D2; i += 128)     b2s[i] = b2[s * D2 + i];
    for (int i = tid; i < 3 * D2 * D1; i += 128) {
        int d2 = i / (D1 * 3);
        int r  = i % (D1 * 3);
        int d1 = r / 3;
        int k  = r % 3;
        w2s[(k * D2 + d2) * D1 + d1] = w2[s * D2 * D1 * 3 + i];
    }
    __syncthreads();

    const int b = blockIdx.x * 128 + tid;

    float xp[L + 2];
    xp[0] = 0.0f; xp[L + 1] = 0.0f;
    #pragma unroll
    for (int l = 0; l < L; ++l) xp[l + 1] = x[(b * S + s) * L + l];

    uint64_t hp[L][D1 / 2];
    #pragma unroll
    for (int l = 0; l < L; ++l) {
        #pragma unroll
        for (int q = 0; q < D1 / 2; ++q) {
            int d1a = 2 * q, d1b = 2 * q + 1;
            float va = b1s[d1a]
                     + w1s[d1a * 3 + 0] * xp[l]
                     + w1s[d1a * 3 + 1] * xp[l + 1]
                     + w1s[d1a * 3 + 2] * xp[l + 2];
            float vb = b1s[d1b]
                     + w1s[d1b * 3 + 0] * xp[l]
                     + w1s[d1b * 3 + 1] * xp[l + 1]
                     + w1s[d1b * 3 + 2] * xp[l + 2];
            hp[l][q] = pk2(gelu_exact(va), gelu_exact(vb));
        }
    }

    __half* outHi = &g_ahi[(size_t)s * KDIM * BATCH + b];
    __half* outLo = &g_alo[(size_t)s * KDIM * BATCH + b];
    for (int d2 = 0; d2 < D2; ++d2) {
        uint64_t accp[L];
        uint64_t init = pk2(b2s[d2], 0.0f);
        #pragma unroll
        for (int l = 0; l < L; ++l) accp[l] = init;

        #pragma unroll
        for (int k = 0; k < 3; ++k) {
            const ulonglong2* wp = (const ulonglong2*)&w2s[(k * D2 + d2) * D1];
            #pragma unroll
            for (int qq = 0; qq < D1 / 4; ++qq) {
                ulonglong2 wv = wp[qq];
                #pragma unroll
                for (int l = 0; l < L; ++l) {
                    int c = l + k - 1;
                    if (c >= 0 && c < L) {
                        accp[l] = fma2(wv.x, hp[c][2 * qq + 0], accp[l]);
                        accp[l] = fma2(wv.y, hp[c][2 * qq + 1], accp[l]);
                    }
                }
            }
        }
        #pragma unroll
        for (int l = 0; l < L; ++l) {
            float lo, hi;
            upk2(lo, hi, accp[l]);
            float v = gelu_exact(lo + hi);
            __half vh = __float2half_rn(v);
            __half vl = __float2half_rn(v - __half2float(vh));
            size_t off = (size_t)(d2 * L + l) * BATCH;
            outHi[off] = vh;
            outLo[off] = vl;
        }
    }
}

// ============================================================================
// K2: per (s,j) sum / sumsq over b — from hi only (lo shifts stats by ~4e-7σ,
//   and stats are used consistently, so this is harmless).  Halves traffic.
// ============================================================================
__global__ void k2_stats()
{
    const int j = blockIdx.x, s = blockIdx.y, tid = threadIdx.x;
    const uint4* ph = (const uint4*)&g_ahi[(size_t)(s * KDIM + j) * BATCH];
    float s1 = 0.0f, s2 = 0.0f;
    for (int i = tid; i < BATCH / 8; i += 256) {
        uint4 a4 = ph[i];
        const uint32_t* aw = (const uint32_t*)&a4;
        #pragma unroll
        for (int w = 0; w < 4; ++w) {
            float2 a = __half22float2(*(const __half2*)&aw[w]);
            s1 += a.x + a.y;
            s2 += a.x * a.x + a.y * a.y;
        }
    }
    __shared__ float r1[256], r2[256];
    r1[tid] = s1; r2[tid] = s2;
    __syncthreads();
    for (int off = 128; off > 0; off >>= 1) {
        if (tid < off) { r1[tid] += r1[tid + off]; r2[tid] += r2[tid + off]; }
        __syncthreads();
    }
    if (tid == 0) {
        g_sum1[s * KDIM + j] = r1[0];
        g_sum2[s * KDIM + j] = r2[0];
    }
}

// ============================================================================
// K3all: fused BN-finalize + weight fp16 + COMPENSATED bias.
// ============================================================================
__global__ __launch_bounds__(KDIM) void k3_all(
    const float* __restrict__ gamma, const float* __restrict__ beta,
    const float* __restrict__ wl,    const float* __restrict__ bl)
{
    const int bid = blockIdx.x, s = blockIdx.y, j = threadIdx.x;  // 320 threads
    __shared__ float sc_s[D2], sh_s[D2];
    if (j < D2) {
        float S1 = 0.0f, S2 = 0.0f;
        #pragma unroll
        for (int l = 0; l < L; ++l) {
            S1 += g_sum1[s * KDIM + j * L + l];
            S2 += g_sum2[s * KDIM + j * L + l];
        }
        const float invn = 1.0f / (float)(BATCH * L);
        float mean = S1 * invn;
        float var  = S2 * invn - mean * mean;
        float inv  = rsqrtf(var + EPSBN);
        float sc   = gamma[s * D2 + j] * inv;
        sc_s[j] = sc;
        sh_s[j] = beta[s * D2 + j] - mean * sc;
    }
    __syncthreads();

    if (bid < NPAD) {
        const int o = bid;
        float v = 0.0f;
        if (o < OUT) v = wl[((size_t)s * OUT + o) * KDIM + j] * sc_s[j / L];
        g_bh[((size_t)(s * NPAD + o)) * KDIM + j] = __float2half_rn(v);
    } else {
        const int o = bid - NPAD;   // < OUT
        float W   = wl[((size_t)s * OUT + o) * KDIM + j] * sc_s[j / L];
        float Blo = W - __half2float(__float2half_rn(W));
        float meanj = g_sum1[s * KDIM + j] * (1.0f / (float)BATCH);
        float v = wl[((size_t)s * OUT + o) * KDIM + j] * sh_s[j / L]
                + Blo * meanj;
        __shared__ float red[KDIM];
        red[j] = v;
        __syncthreads();
        if (j < 64)  red[j] += red[j + 256];
        __syncthreads();
        if (j < 128) red[j] += red[j + 128];
        __syncthreads();
        if (j < 64)  red[j] += red[j + 64];
        __syncthreads();
        if (j < 32) {
            float xv = red[j] + red[j + 32];
            #pragma unroll
            for (int off = 16; off > 0; off >>= 1)
                xv += __shfl_down_sync(0xffffffffu, xv, off);
            if (j == 0) g_bias[s * OUT + o] = bl[s * OUT + o] + xv;
        }
    }
}

// ============================================================================
// K6: HMMA 2-term fp16 split-GEMM, CTA 64x96, BK=64, 2 stages, 3 CTAs/SM.
//   Warp tile 16x48 (24 acc regs).  Commit cadence kept in the tail so
//   cp_wait<1> always guarantees the current stage has landed.
// ============================================================================
__global__ __launch_bounds__(256, 3) void k6_gemm(float* __restrict__ out)
{
    extern __shared__ __align__(16) char dyn[];
    const uint32_t sbase = smem_u32(dyn);

    const int tid  = threadIdx.x;
    const int wid  = tid >> 5;
    const int lane = tid & 31;
    const int nt = blockIdx.x * BN;   // fastest -> A L2 reuse
    const int bt = blockIdx.y * BM;
    const int s  = blockIdx.z;

    const int wm = (wid & 3) * 16;    // warp m offset (16-row tiles)
    const int wn = (wid >> 2) * 48;   // warp n offset

    const __half* Ah = g_ahi + (size_t)s * KDIM * BATCH + bt;   // + j*BATCH
    const __half* Al = g_alo + (size_t)s * KDIM * BATCH + bt;
    const __half* Bp = g_bh  + ((size_t)(s * NPAD + nt)) * KDIM;

    float c[6][4];
    #pragma unroll
    for (int j = 0; j < 6; ++j)
        #pragma unroll
        for (int k = 0; k < 4; ++k) c[j][k] = 0.0f;

    auto load_stage = [&](int chunk) {
        const uint32_t st = sbase + (uint32_t)(chunk & (NSTAGE - 1)) * STAGE_BYTES;
        const int coff = chunk * BK;
        // A hi/lo: 64 j-rows x 8 granules of 16B (8 b's each; 64 b cols)
        #pragma unroll
        for (int u = tid; u < BK * 8; u += 256) {
            int row = u >> 3, g = u & 7;
            uint32_t so = swz128(row, g);
            cp16(st + so,           Ah + (size_t)(coff + row) * BATCH + g * 8);
            cp16(st + A_BYTES + so, Al + (size_t)(coff + row) * BATCH + g * 8);
        }
        // B: 96 o-rows x 8 granules of 16B (64 k-halves per row)
        #pragma unroll
        for (int u = tid; u < BN * 8; u += 256) {
            int row = u >> 3, g = u & 7;
            cp16(st + 2 * A_BYTES + swz128(row, g),
                 (const char*)(Bp + (size_t)row * KDIM + coff) + g * 16);
        }
        cp_commit();
    };

    load_stage(0);
    load_stage(1);

    #pragma unroll 1
    for (int ch = 0; ch < NCHUNK; ++ch) {
        cp_wait<1>();          // with per-iter commits: stage ch landed
        __syncthreads();

        const uint32_t st = sbase + (uint32_t)(ch & (NSTAGE - 1)) * STAGE_BYTES;
        const uint32_t aH = st;
        const uint32_t aL = st + A_BYTES;
        const uint32_t bS = st + 2 * A_BYTES;

        #pragma unroll
        for (int ks = 0; ks < 4; ++ks) {
            // A fragments via ldmatrix.trans: 16 m-rows x 16 k for this warp
            uint32_t ahf[4], alf[4];
            {
                int jr = ks * 16 + ((lane >> 4) << 3) + (lane & 7);
                int g  = wm / 8 + ((lane >> 3) & 1);     // b-granule
                uint32_t so = swz128(jr, g);
                ldm_x4_t(ahf[0], ahf[1], ahf[2], ahf[3], aH + so);
                ldm_x4_t(alf[0], alf[1], alf[2], alf[3], aL + so);
            }
            uint32_t bf[6][2];
            #pragma unroll
            for (int p = 0; p < 3; ++p) {
                int row = wn + p * 16 + ((lane >> 4) << 3) + (lane & 7);
                int g   = ks * 2 + ((lane >> 3) & 1);
                ldm_x4(bf[2 * p][0], bf[2 * p][1], bf[2 * p + 1][0], bf[2 * p + 1][1],
                       bS + swz128(row, g));
            }
            #pragma unroll
            for (int nf = 0; nf < 6; ++nf)
                mma16816(c[nf], ahf, bf[nf]);
            #pragma unroll
            for (int nf = 0; nf < 6; ++nf)
                mma16816(c[nf], alf, bf[nf]);
        }

        __syncthreads();       // everyone done reading stage ch before overwrite
        if (ch + 2 < NCHUNK) load_stage(ch + 2);
        else                 cp_commit();          // keep group cadence in tail
    }

    // ---- epilogue: add bias, SCALAR stores (OUT=541 odd -> rows not 8B-aligned)
    const int mrow = lane >> 2;
    const int ncol = (lane & 3) * 2;
    #pragma unroll
    for (int half = 0; half < 2; ++half) {
        int m = bt + wm + mrow + half * 8;
        float* orow = out + ((size_t)m * S + s) * OUT;
        #pragma unroll
        for (int nf = 0; nf < 6; ++nf) {
            int o = nt + wn + nf * 8 + ncol;
            if (o < OUT)     orow[o]     = c[nf][2 * half + 0] + g_bias[s * OUT + o];
            if (o + 1 < OUT) orow[o + 1] = c[nf][2 * half + 1] + g_bias[s * OUT + o + 1];
        }
    }
}

// ============================================================================
extern "C" void kernel_launch(void* const* d_in, const int* in_sizes, int n_in,
                              void* d_out, int out_size)
{
    const float* x     = (const float*)d_in[0];
    const float* w1    = (const float*)d_in[1];
    const float* b1    = (const float*)d_in[2];
    const float* w2    = (const float*)d_in[3];
    const float* b2    = (const float*)d_in[4];
    const float* gamma = (const float*)d_in[5];
    const float* beta  = (const float*)d_in[6];
    const float* wl    = (const float*)d_in[7];
    const float* bl    = (const float*)d_in[8];
    float* out = (float*)d_out;

    cudaFuncSetAttribute(k6_gemm, cudaFuncAttributeMaxDynamicSharedMemorySize, DSMEM);

    k1_conv <<<dim3(BATCH / 128, S), 128>>>(x, w1, b1, w2, b2);
    k2_stats<<<dim3(KDIM, S), 256>>>();
    k3_all  <<<dim3(NPAD + OUT, S), KDIM>>>(gamma, beta, wl, bl);
    k6_gemm <<<dim3(NPAD / BN, BATCH / BM, S), 256, DSMEM>>>(out);
}